// round 6
// baseline (speedup 1.0000x reference)
#include <cuda_runtime.h>
#include <cuda_bf16.h>
#include <cstdint>

#define NFEAT 512
#define HID   128
#define NCLS  64
#define NMAX  50048
#define EMAX  640000

// ---------------- device scratch ----------------
__device__ float g_dinv[NMAX];
__device__ int   g_cnt [NMAX];
__device__ int   g_excl[NMAX];
__device__ int   g_bsum[256];
__device__ int   g_boff[256];
__device__ int   g_rs  [NMAX + 1];
__device__ int   g_cur [NMAX];
__device__ int2  g_csr [EMAX];
__device__ float g_H1  [(size_t)NMAX * HID];
__device__ float g_H2  [(size_t)NMAX * NCLS];
__device__ __nv_bfloat16 g_Bh[HID * NFEAT];
__device__ __nv_bfloat16 g_Bl[HID * NFEAT];
__device__ __nv_bfloat16 g_B2h[NCLS * HID];
__device__ __nv_bfloat16 g_B2l[NCLS * HID];

// ==================== helpers ====================
__device__ __forceinline__ uint32_t smem_u32(const void* p) {
    uint32_t a;
    asm("{ .reg .u64 t; cvta.to.shared.u64 t, %1; cvt.u32.u64 %0, t; }"
        : "=r"(a) : "l"(p));
    return a;
}
__device__ __forceinline__ void ldm_x4(uint32_t& r0, uint32_t& r1,
                                       uint32_t& r2, uint32_t& r3, uint32_t addr) {
    asm volatile("ldmatrix.sync.aligned.m8n8.x4.shared.b16 {%0,%1,%2,%3}, [%4];"
                 : "=r"(r0), "=r"(r1), "=r"(r2), "=r"(r3) : "r"(addr));
}
__device__ __forceinline__ void mma_bf16(float& d0, float& d1, float& d2, float& d3,
                                         uint32_t a0, uint32_t a1, uint32_t a2, uint32_t a3,
                                         uint32_t b0, uint32_t b1) {
    asm volatile(
        "mma.sync.aligned.m16n8k16.row.col.f32.bf16.bf16.f32 "
        "{%0,%1,%2,%3}, {%4,%5,%6,%7}, {%8,%9}, {%0,%1,%2,%3};"
        : "+f"(d0), "+f"(d1), "+f"(d2), "+f"(d3)
        : "r"(a0), "r"(a1), "r"(a2), "r"(a3), "r"(b0), "r"(b1));
}
__device__ __forceinline__ void cp16(uint32_t dst, const void* src) {
    asm volatile("cp.async.cg.shared.global [%0], [%1], 16;" :: "r"(dst), "l"(src));
}
#define CP_COMMIT() asm volatile("cp.async.commit_group;" ::: "memory")
#define CP_WAIT0()  asm volatile("cp.async.wait_group 0;" ::: "memory")

// ==================== CSR build ====================
__global__ void k_cnt_init(int N) {
    int i = blockIdx.x * blockDim.x + threadIdx.x;
    if (i < N) g_cnt[i] = 0;
}
__global__ void k_cnt_acc(const int* __restrict__ ei, int E) {
    int e = blockIdx.x * blockDim.x + threadIdx.x;
    if (e < E) atomicAdd(&g_cnt[ei[E + e]], 1);
}
__global__ void k_scan1(int N) {
    __shared__ int sh[256];
    int i = blockIdx.x * 256 + threadIdx.x;
    int v = (i < N) ? g_cnt[i] : 0;
    if (i < N) g_dinv[i] = rsqrtf((float)(v + 1));
    sh[threadIdx.x] = v;
    __syncthreads();
    #pragma unroll
    for (int off = 1; off < 256; off <<= 1) {
        int t = (threadIdx.x >= off) ? sh[threadIdx.x - off] : 0;
        __syncthreads();
        sh[threadIdx.x] += t;
        __syncthreads();
    }
    if (i < N) g_excl[i] = sh[threadIdx.x] - v;
    if (threadIdx.x == 255) g_bsum[blockIdx.x] = sh[255];
}
__global__ void k_scan2(int nb, int N, int E) {
    __shared__ int sh[256];
    int v = (threadIdx.x < nb) ? g_bsum[threadIdx.x] : 0;
    sh[threadIdx.x] = v;
    __syncthreads();
    #pragma unroll
    for (int off = 1; off < 256; off <<= 1) {
        int t = (threadIdx.x >= off) ? sh[threadIdx.x - off] : 0;
        __syncthreads();
        sh[threadIdx.x] += t;
        __syncthreads();
    }
    if (threadIdx.x < nb) g_boff[threadIdx.x] = sh[threadIdx.x] - v;
    if (threadIdx.x == 0) g_rs[N] = E;
}
__global__ void k_scan3(int N) {
    int i = blockIdx.x * blockDim.x + threadIdx.x;
    if (i < N) {
        int r = g_excl[i] + g_boff[i >> 8];
        g_rs[i]  = r;
        g_cur[i] = r;
    }
}
__global__ void k_scatter(const int* __restrict__ ei, int E) {
    int e = blockIdx.x * blockDim.x + threadIdx.x;
    if (e >= E) return;
    int s = ei[e];
    int d = ei[E + e];
    int pos = atomicAdd(&g_cur[d], 1);
    g_csr[pos] = make_int2(s, __float_as_int(g_dinv[s] * g_dinv[d]));
}

// ==================== weight prep ====================
__global__ void k_prepW(const float* __restrict__ W) {
    int t = blockIdx.x * blockDim.x + threadIdx.x;
    if (t >= NFEAT * HID) return;
    int k = t >> 7;
    int n = t & 127;
    float v = W[t];
    __nv_bfloat16 h = __float2bfloat16(v);
    __nv_bfloat16 l = __float2bfloat16(v - __bfloat162float(h));
    g_Bh[n * NFEAT + k] = h;
    g_Bl[n * NFEAT + k] = l;
}
__global__ void k_prepW2(const float* __restrict__ W) {
    int t = blockIdx.x * blockDim.x + threadIdx.x;
    if (t >= HID * NCLS) return;
    int k = t >> 6;
    int n = t & 63;
    float v = W[t];
    __nv_bfloat16 h = __float2bfloat16(v);
    __nv_bfloat16 l = __float2bfloat16(v - __bfloat162float(h));
    g_B2h[n * HID + k] = h;
    g_B2l[n * HID + k] = l;
}

// ==================== GEMM1 via mma.sync bf16 split ====================
#define STRB   80
#define BUFSZ  40960
#define OFF_AL 10240
#define OFF_BH 20480
#define OFF_BL 30720
#define NCHUNK (NFEAT / 32)     // 16
#define GSMEM_BYTES (2 * BUFSZ)

extern __shared__ __align__(128) unsigned char s_dyn[];

__global__ void __launch_bounds__(256) k_gemm1_mma(const float* __restrict__ X, int N) {
    uint32_t sb = smem_u32(s_dyn);
    int tid  = threadIdx.x;
    int wid  = tid >> 5;
    int lane = tid & 31;
    int warp_m = (wid & 3) * 32;
    int warp_n = (wid >> 2) * 64;
    int rowBase = blockIdx.x * 128;

    float acc[2][8][4];
    #pragma unroll
    for (int mt = 0; mt < 2; mt++)
        #pragma unroll
        for (int nt = 0; nt < 8; nt++)
            #pragma unroll
            for (int j = 0; j < 4; j++) acc[mt][nt][j] = 0.0f;

    float4 xs[4];
    int xrow = tid >> 3;
    int xseg = tid & 7;
    int bn   = tid >> 2;
    int bseg = tid & 3;

    #define LOAD_X(c)                                                          \
        {                                                                      \
            _Pragma("unroll")                                                  \
            for (int i = 0; i < 4; i++) {                                      \
                int row = xrow + 32 * i;                                       \
                int grow = rowBase + row;                                      \
                if (grow > N - 1) grow = N - 1;                                \
                xs[i] = *(const float4*)(X + (size_t)grow * NFEAT + (c) * 32 + xseg * 4); \
            }                                                                  \
        }
    #define CP_B(c, b)                                                         \
        {                                                                      \
            _Pragma("unroll")                                                  \
            for (int i = 0; i < 2; i++) {                                      \
                int n = bn + 64 * i;                                           \
                uint32_t dst = sb + (b) * BUFSZ + OFF_BH + n * STRB + bseg * 16; \
                cp16(dst, g_Bh + (size_t)n * NFEAT + (c) * 32 + bseg * 8);      \
                cp16(dst + (OFF_BL - OFF_BH),                                   \
                     g_Bl + (size_t)n * NFEAT + (c) * 32 + bseg * 8);           \
            }                                                                  \
        }
    #define STORE_A(b)                                                         \
        {                                                                      \
            unsigned char* base = s_dyn + (b) * BUFSZ;                         \
            _Pragma("unroll")                                                  \
            for (int i = 0; i < 4; i++) {                                      \
                int row = xrow + 32 * i;                                       \
                float f[4] = {xs[i].x, xs[i].y, xs[i].z, xs[i].w};             \
                uint32_t hi[2], lo[2];                                         \
                _Pragma("unroll")                                              \
                for (int j = 0; j < 2; j++) {                                  \
                    __nv_bfloat16 ha = __float2bfloat16(f[2*j]);               \
                    __nv_bfloat16 hb = __float2bfloat16(f[2*j+1]);             \
                    __nv_bfloat162 hp; hp.x = ha; hp.y = hb;                   \
                    __nv_bfloat162 lp = __floats2bfloat162_rn(                 \
                        f[2*j]   - __bfloat162float(ha),                       \
                        f[2*j+1] - __bfloat162float(hb));                      \
                    hi[j] = *(uint32_t*)&hp;                                   \
                    lo[j] = *(uint32_t*)&lp;                                   \
                }                                                              \
                uint32_t off = row * STRB + xseg * 8;                          \
                *(uint2*)(base + off)          = make_uint2(hi[0], hi[1]);     \
                *(uint2*)(base + OFF_AL + off) = make_uint2(lo[0], lo[1]);     \
            }                                                                  \
        }

    CP_B(0, 0); CP_COMMIT();
    LOAD_X(0);
    STORE_A(0);
    CP_WAIT0();
    __syncthreads();

    uint32_t aRowOff = (warp_m + (lane & 15)) * STRB + ((lane & 16) ? 16 : 0);
    uint32_t bRowSel = (lane & 7) + ((lane & 16) ? 8 : 0);
    uint32_t bKoff   = (lane & 8) ? 16 : 0;

    #pragma unroll 1
    for (int c = 0; c < NCHUNK; c++) {
        int cur = c & 1;
        if (c + 1 < NCHUNK) {
            CP_B(c + 1, cur ^ 1); CP_COMMIT();
            LOAD_X(c + 1);
        }

        uint32_t base = sb + cur * BUFSZ;
        #pragma unroll
        for (int ka = 0; ka < 2; ka++) {
            uint32_t k0b = ka * 32;

            uint32_t ah[2][4], al[2][4];
            #pragma unroll
            for (int mt = 0; mt < 2; mt++) {
                uint32_t aaddr = base + aRowOff + mt * (16 * STRB) + k0b;
                ldm_x4(ah[mt][0], ah[mt][1], ah[mt][2], ah[mt][3], aaddr);
                ldm_x4(al[mt][0], al[mt][1], al[mt][2], al[mt][3], aaddr + OFF_AL);
            }

            uint32_t bh[8][2], bl[8][2];
            #pragma unroll
            for (int np = 0; np < 4; np++) {
                uint32_t brow = warp_n + np * 16 + bRowSel;
                uint32_t baddr = base + OFF_BH + brow * STRB + k0b + bKoff;
                ldm_x4(bh[2*np][0], bh[2*np][1], bh[2*np+1][0], bh[2*np+1][1], baddr);
                ldm_x4(bl[2*np][0], bl[2*np][1], bl[2*np+1][0], bl[2*np+1][1],
                       baddr + (OFF_BL - OFF_BH));
            }

            #pragma unroll
            for (int mt = 0; mt < 2; mt++)
                #pragma unroll
                for (int nt = 0; nt < 8; nt++) {
                    mma_bf16(acc[mt][nt][0], acc[mt][nt][1], acc[mt][nt][2], acc[mt][nt][3],
                             ah[mt][0], ah[mt][1], ah[mt][2], ah[mt][3],
                             bh[nt][0], bh[nt][1]);
                    mma_bf16(acc[mt][nt][0], acc[mt][nt][1], acc[mt][nt][2], acc[mt][nt][3],
                             ah[mt][0], ah[mt][1], ah[mt][2], ah[mt][3],
                             bl[nt][0], bl[nt][1]);
                    mma_bf16(acc[mt][nt][0], acc[mt][nt][1], acc[mt][nt][2], acc[mt][nt][3],
                             al[mt][0], al[mt][1], al[mt][2], al[mt][3],
                             bh[nt][0], bh[nt][1]);
                }
        }

        if (c + 1 < NCHUNK) {
            STORE_A(cur ^ 1);
            CP_WAIT0();
        }
        __syncthreads();
    }

    int r0 = rowBase + warp_m + (lane >> 2);
    int cc = warp_n + 2 * (lane & 3);
    #pragma unroll
    for (int mt = 0; mt < 2; mt++) {
        int ra = r0 + mt * 16;
        int rb = ra + 8;
        #pragma unroll
        for (int nt = 0; nt < 8; nt++) {
            int col = cc + nt * 8;
            if (ra < N)
                *(float2*)(g_H1 + (size_t)ra * HID + col) =
                    make_float2(acc[mt][nt][0], acc[mt][nt][1]);
            if (rb < N)
                *(float2*)(g_H1 + (size_t)rb * HID + col) =
                    make_float2(acc[mt][nt][2], acc[mt][nt][3]);
        }
    }
    #undef LOAD_X
    #undef CP_B
    #undef STORE_A
}

// ==================== fused agg1 + gemm2 ====================
// Block: 128 nodes. Phase 1: warp-per-node aggregation (relu(b1 + dinv^2*H1 + gather))
// converted to bf16 hi/lo in smem. Phase 2: MMA with W2 (hi/lo from smem) -> H2.
#define FA_STR 272
#define FA_H   0
#define FA_L   34816
#define FB_H   69632
#define FB_L   87040
#define FSMEM  104448

__global__ void __launch_bounds__(256) k_agg1_gemm2(const float* __restrict__ b1, int N) {
    uint32_t sb = smem_u32(s_dyn);
    int tid  = threadIdx.x;
    int wid  = tid >> 5;
    int lane = tid & 31;
    int tileBase = blockIdx.x * 128;

    // ---- async load B2 hi/lo ----
    {
        int r   = tid >> 2;
        int sgr = tid & 3;
        #pragma unroll
        for (int j = 0; j < 4; j++) {
            int seg = sgr + j * 4;
            uint32_t dst = sb + FB_H + r * FA_STR + seg * 16;
            cp16(dst, g_B2h + (size_t)r * HID + seg * 8);
            cp16(dst + (FB_L - FB_H), g_B2l + (size_t)r * HID + seg * 8);
        }
        CP_COMMIT();
    }

    // ---- phase 1: aggregation ----
    #pragma unroll 1
    for (int rp = 0; rp < 16; rp++) {
        int row  = rp * 8 + wid;
        int node = tileBase + row;
        int gn   = node < N ? node : N - 1;

        float di = g_dinv[gn];
        float s2 = di * di;
        float4 acc = ((const float4*)b1)[lane];
        float4 h   = *((const float4*)(g_H1 + (size_t)gn * HID) + lane);
        acc.x += s2 * h.x; acc.y += s2 * h.y; acc.z += s2 * h.z; acc.w += s2 * h.w;

        int e   = g_rs[gn];
        int end = g_rs[gn + 1];
        for (; e + 1 < end; e += 2) {
            int2 p0 = g_csr[e];
            int2 p1 = g_csr[e + 1];
            float n0 = __int_as_float(p0.y);
            float n1 = __int_as_float(p1.y);
            float4 v0 = __ldg((const float4*)(g_H1 + (size_t)p0.x * HID) + lane);
            float4 v1 = __ldg((const float4*)(g_H1 + (size_t)p1.x * HID) + lane);
            acc.x += n0 * v0.x; acc.y += n0 * v0.y; acc.z += n0 * v0.z; acc.w += n0 * v0.w;
            acc.x += n1 * v1.x; acc.y += n1 * v1.y; acc.z += n1 * v1.z; acc.w += n1 * v1.w;
        }
        if (e < end) {
            int2 p0 = g_csr[e];
            float n0 = __int_as_float(p0.y);
            float4 v0 = __ldg((const float4*)(g_H1 + (size_t)p0.x * HID) + lane);
            acc.x += n0 * v0.x; acc.y += n0 * v0.y; acc.z += n0 * v0.z; acc.w += n0 * v0.w;
        }

        acc.x = fmaxf(acc.x, 0.f); acc.y = fmaxf(acc.y, 0.f);
        acc.z = fmaxf(acc.z, 0.f); acc.w = fmaxf(acc.w, 0.f);

        // split to bf16 hi/lo, store smem
        float f[4] = {acc.x, acc.y, acc.z, acc.w};
        uint32_t hi[2], lo[2];
        #pragma unroll
        for (int j = 0; j < 2; j++) {
            __nv_bfloat16 ha = __float2bfloat16(f[2*j]);
            __nv_bfloat16 hb = __float2bfloat16(f[2*j+1]);
            __nv_bfloat162 hp; hp.x = ha; hp.y = hb;
            __nv_bfloat162 lp = __floats2bfloat162_rn(
                f[2*j]   - __bfloat162float(ha),
                f[2*j+1] - __bfloat162float(hb));
            hi[j] = *(uint32_t*)&hp;
            lo[j] = *(uint32_t*)&lp;
        }
        uint32_t off = row * FA_STR + lane * 8;
        *(uint2*)(s_dyn + FA_H + off) = make_uint2(hi[0], hi[1]);
        *(uint2*)(s_dyn + FA_L + off) = make_uint2(lo[0], lo[1]);
    }

    CP_WAIT0();
    __syncthreads();

    // ---- phase 2: MMA (128x64, K=128) ----
    int warp_m = (wid & 3) * 32;
    int warp_n = (wid >> 2) * 32;

    float acc[2][4][4];
    #pragma unroll
    for (int mt = 0; mt < 2; mt++)
        #pragma unroll
        for (int nt = 0; nt < 4; nt++)
            #pragma unroll
            for (int j = 0; j < 4; j++) acc[mt][nt][j] = 0.0f;

    uint32_t aRowOff = (warp_m + (lane & 15)) * FA_STR + ((lane & 16) ? 16 : 0);
    uint32_t bRowSel = (lane & 7) + ((lane & 16) ? 8 : 0);
    uint32_t bKoff   = (lane & 8) ? 16 : 0;

    #pragma unroll
    for (int kk = 0; kk < 8; kk++) {            // 8 x k16 = K128
        uint32_t k0b = kk * 32;

        uint32_t ah[2][4], al[2][4];
        #pragma unroll
        for (int mt = 0; mt < 2; mt++) {
            uint32_t aaddr = sb + FA_H + aRowOff + mt * (16 * FA_STR) + k0b;
            ldm_x4(ah[mt][0], ah[mt][1], ah[mt][2], ah[mt][3], aaddr);
            ldm_x4(al[mt][0], al[mt][1], al[mt][2], al[mt][3], aaddr + (FA_L - FA_H));
        }

        uint32_t bh[4][2], bl[4][2];
        #pragma unroll
        for (int np = 0; np < 2; np++) {
            uint32_t brow = warp_n + np * 16 + bRowSel;
            uint32_t baddr = sb + FB_H + brow * FA_STR + k0b + bKoff;
            ldm_x4(bh[2*np][0], bh[2*np][1], bh[2*np+1][0], bh[2*np+1][1], baddr);
            ldm_x4(bl[2*np][0], bl[2*np][1], bl[2*np+1][0], bl[2*np+1][1],
                   baddr + (FB_L - FB_H));
        }

        #pragma unroll
        for (int mt = 0; mt < 2; mt++)
            #pragma unroll
            for (int nt = 0; nt < 4; nt++) {
                mma_bf16(acc[mt][nt][0], acc[mt][nt][1], acc[mt][nt][2], acc[mt][nt][3],
                         ah[mt][0], ah[mt][1], ah[mt][2], ah[mt][3],
                         bh[nt][0], bh[nt][1]);
                mma_bf16(acc[mt][nt][0], acc[mt][nt][1], acc[mt][nt][2], acc[mt][nt][3],
                         ah[mt][0], ah[mt][1], ah[mt][2], ah[mt][3],
                         bl[nt][0], bl[nt][1]);
                mma_bf16(acc[mt][nt][0], acc[mt][nt][1], acc[mt][nt][2], acc[mt][nt][3],
                         al[mt][0], al[mt][1], al[mt][2], al[mt][3],
                         bh[nt][0], bh[nt][1]);
            }
    }

    int r0 = tileBase + warp_m + (lane >> 2);
    int cc = warp_n + 2 * (lane & 3);
    #pragma unroll
    for (int mt = 0; mt < 2; mt++) {
        int ra = r0 + mt * 16;
        int rb = ra + 8;
        #pragma unroll
        for (int nt = 0; nt < 4; nt++) {
            int col = cc + nt * 8;
            if (ra < N)
                *(float2*)(g_H2 + (size_t)ra * NCLS + col) =
                    make_float2(acc[mt][nt][0], acc[mt][nt][1]);
            if (rb < N)
                *(float2*)(g_H2 + (size_t)rb * NCLS + col) =
                    make_float2(acc[mt][nt][2], acc[mt][nt][3]);
        }
    }
}

// ==================== layer-2 aggregation (16 lanes per node) ====================
__global__ __launch_bounds__(256) void k_agg2(const float* __restrict__ b2,
                                              float* __restrict__ out, int N) {
    int t = blockIdx.x * blockDim.x + threadIdx.x;
    int i = t >> 4;
    int c = t & 15;
    if (i >= N) return;

    float di = g_dinv[i];
    float s2 = di * di;
    float4 acc = ((const float4*)b2)[c];
    float4 h   = *((const float4*)(g_H2 + (size_t)i * NCLS) + c);
    acc.x += s2 * h.x; acc.y += s2 * h.y; acc.z += s2 * h.z; acc.w += s2 * h.w;

    int e   = g_rs[i];
    int end = g_rs[i + 1];
    for (; e + 1 < end; e += 2) {
        int2 p0 = g_csr[e];
        int2 p1 = g_csr[e + 1];
        float n0 = __int_as_float(p0.y);
        float n1 = __int_as_float(p1.y);
        float4 v0 = __ldg((const float4*)(g_H2 + (size_t)p0.x * NCLS) + c);
        float4 v1 = __ldg((const float4*)(g_H2 + (size_t)p1.x * NCLS) + c);
        acc.x += n0 * v0.x; acc.y += n0 * v0.y; acc.z += n0 * v0.z; acc.w += n0 * v0.w;
        acc.x += n1 * v1.x; acc.y += n1 * v1.y; acc.z += n1 * v1.z; acc.w += n1 * v1.w;
    }
    if (e < end) {
        int2 p0 = g_csr[e];
        float n0 = __int_as_float(p0.y);
        float4 v0 = __ldg((const float4*)(g_H2 + (size_t)p0.x * NCLS) + c);
        acc.x += n0 * v0.x; acc.y += n0 * v0.y; acc.z += n0 * v0.z; acc.w += n0 * v0.w;
    }

    *((float4*)(out + (size_t)i * NCLS) + c) = acc;
}

// ==================== launch ====================
struct AuxObjs {
    cudaStream_t s1;
    cudaEvent_t  e0, e1;
    AuxObjs() {
        cudaStreamCreateWithFlags(&s1, cudaStreamNonBlocking);
        cudaEventCreateWithFlags(&e0, cudaEventDisableTiming);
        cudaEventCreateWithFlags(&e1, cudaEventDisableTiming);
    }
};

extern "C" void kernel_launch(void* const* d_in, const int* in_sizes, int n_in,
                              void* d_out, int out_size) {
    static AuxObjs aux;

    const float* x  = (const float*)d_in[0];
    const int*   ei = (const int*)  d_in[1];
    const float* W1 = (const float*)d_in[2];
    const float* b1 = (const float*)d_in[3];
    const float* W2 = (const float*)d_in[4];
    const float* b2 = (const float*)d_in[5];
    float* out = (float*)d_out;

    int N = in_sizes[0] / NFEAT;   // 50000
    int E = in_sizes[1] / 2;       // 640000
    int nb = (N + 255) / 256;

    cudaFuncSetAttribute(k_gemm1_mma, cudaFuncAttributeMaxDynamicSharedMemorySize,
                         GSMEM_BYTES);
    cudaFuncSetAttribute(k_agg1_gemm2, cudaFuncAttributeMaxDynamicSharedMemorySize,
                         FSMEM);

    // Fork CSR branch onto s1.
    cudaEventRecord(aux.e0, 0);
    cudaStreamWaitEvent(aux.s1, aux.e0, 0);

    k_cnt_init<<<(N + 255) / 256, 256, 0, aux.s1>>>(N);          // launch 1
    k_cnt_acc <<<(E + 255) / 256, 256, 0, aux.s1>>>(ei, E);      // launch 2
    k_prepW   <<<(NFEAT * HID + 255) / 256, 256>>>(W1);          // launch 3 (main)
    k_gemm1_mma<<<(N + 127) / 128, 256, GSMEM_BYTES>>>(x, N);    // launch 4 (profiled)
    k_scan1   <<<nb, 256, 0, aux.s1>>>(N);                       // launch 5
    k_scan2   <<<1, 256, 0, aux.s1>>>(nb, N, E);                 // launch 6
    k_scan3   <<<nb, 256, 0, aux.s1>>>(N);                       // launch 7
    k_scatter <<<(E + 255) / 256, 256, 0, aux.s1>>>(ei, E);      // launch 8
    k_prepW2  <<<(HID * NCLS + 255) / 256, 256>>>(W2);           // launch 9 (main)
    cudaEventRecord(aux.e1, aux.s1);
    cudaStreamWaitEvent(0, aux.e1, 0);

    k_agg1_gemm2<<<(N + 127) / 128, 256, FSMEM>>>(b1, N);        // launch 10
    k_agg2      <<<(N * 16 + 255) / 256, 256>>>(b2, out, N);     // launch 11
}

// round 7
// speedup vs baseline: 1.2654x; 1.2654x over previous
#include <cuda_runtime.h>
#include <cuda_bf16.h>
#include <cstdint>

#define NFEAT 512
#define HID   128
#define NCLS  64
#define NMAX  50048
#define EMAX  640000

// ---------------- device scratch ----------------
__device__ float g_dinv[NMAX];
__device__ int   g_cnt [NMAX];
__device__ int   g_excl[NMAX];
__device__ int   g_bsum[256];
__device__ int   g_boff[256];
__device__ int   g_rs  [NMAX + 1];
__device__ int   g_cur [NMAX];
__device__ int2  g_csr [EMAX];
__device__ float g_H1  [(size_t)NMAX * HID];
__device__ float g_agg1[(size_t)NMAX * HID];
__device__ float g_H2  [(size_t)NMAX * NCLS];
__device__ __nv_bfloat16 g_Bh[HID * NFEAT];
__device__ __nv_bfloat16 g_Bl[HID * NFEAT];
__device__ __nv_bfloat16 g_B2h[NCLS * HID];
__device__ __nv_bfloat16 g_B2l[NCLS * HID];

// ==================== helpers ====================
__device__ __forceinline__ uint32_t smem_u32(const void* p) {
    uint32_t a;
    asm("{ .reg .u64 t; cvta.to.shared.u64 t, %1; cvt.u32.u64 %0, t; }"
        : "=r"(a) : "l"(p));
    return a;
}
__device__ __forceinline__ void ldm_x4(uint32_t& r0, uint32_t& r1,
                                       uint32_t& r2, uint32_t& r3, uint32_t addr) {
    asm volatile("ldmatrix.sync.aligned.m8n8.x4.shared.b16 {%0,%1,%2,%3}, [%4];"
                 : "=r"(r0), "=r"(r1), "=r"(r2), "=r"(r3) : "r"(addr));
}
__device__ __forceinline__ void mma_bf16(float& d0, float& d1, float& d2, float& d3,
                                         uint32_t a0, uint32_t a1, uint32_t a2, uint32_t a3,
                                         uint32_t b0, uint32_t b1) {
    asm volatile(
        "mma.sync.aligned.m16n8k16.row.col.f32.bf16.bf16.f32 "
        "{%0,%1,%2,%3}, {%4,%5,%6,%7}, {%8,%9}, {%0,%1,%2,%3};"
        : "+f"(d0), "+f"(d1), "+f"(d2), "+f"(d3)
        : "r"(a0), "r"(a1), "r"(a2), "r"(a3), "r"(b0), "r"(b1));
}
__device__ __forceinline__ void cp16(uint32_t dst, const void* src) {
    asm volatile("cp.async.cg.shared.global [%0], [%1], 16;" :: "r"(dst), "l"(src));
}
#define CP_COMMIT() asm volatile("cp.async.commit_group;" ::: "memory")
#define CP_WAIT0()  asm volatile("cp.async.wait_group 0;" ::: "memory")

// ==================== CSR build ====================
__global__ void k_cnt_init(int N) {
    int i = blockIdx.x * blockDim.x + threadIdx.x;
    if (i < N) g_cnt[i] = 0;
}
__global__ void k_cnt_acc(const int* __restrict__ ei, int E) {
    int e = blockIdx.x * blockDim.x + threadIdx.x;
    if (e < E) atomicAdd(&g_cnt[ei[E + e]], 1);
}
__global__ void k_scan1(int N) {
    __shared__ int sh[256];
    int i = blockIdx.x * 256 + threadIdx.x;
    int v = (i < N) ? g_cnt[i] : 0;
    if (i < N) g_dinv[i] = rsqrtf((float)(v + 1));
    sh[threadIdx.x] = v;
    __syncthreads();
    #pragma unroll
    for (int off = 1; off < 256; off <<= 1) {
        int t = (threadIdx.x >= off) ? sh[threadIdx.x - off] : 0;
        __syncthreads();
        sh[threadIdx.x] += t;
        __syncthreads();
    }
    if (i < N) g_excl[i] = sh[threadIdx.x] - v;
    if (threadIdx.x == 255) g_bsum[blockIdx.x] = sh[255];
}
__global__ void k_scan2(int nb, int N, int E) {
    __shared__ int sh[256];
    int v = (threadIdx.x < nb) ? g_bsum[threadIdx.x] : 0;
    sh[threadIdx.x] = v;
    __syncthreads();
    #pragma unroll
    for (int off = 1; off < 256; off <<= 1) {
        int t = (threadIdx.x >= off) ? sh[threadIdx.x - off] : 0;
        __syncthreads();
        sh[threadIdx.x] += t;
        __syncthreads();
    }
    if (threadIdx.x < nb) g_boff[threadIdx.x] = sh[threadIdx.x] - v;
    if (threadIdx.x == 0) g_rs[N] = E;
}
__global__ void k_scan3(int N) {
    int i = blockIdx.x * blockDim.x + threadIdx.x;
    if (i < N) {
        int r = g_excl[i] + g_boff[i >> 8];
        g_rs[i]  = r;
        g_cur[i] = r;
    }
}
__global__ void k_scatter(const int* __restrict__ ei, int E) {
    int e = blockIdx.x * blockDim.x + threadIdx.x;
    if (e >= E) return;
    int s = ei[e];
    int d = ei[E + e];
    int pos = atomicAdd(&g_cur[d], 1);
    g_csr[pos] = make_int2(s, __float_as_int(g_dinv[s] * g_dinv[d]));
}

// ==================== weight prep ====================
__global__ void k_prepW(const float* __restrict__ W) {
    int t = blockIdx.x * blockDim.x + threadIdx.x;
    if (t >= NFEAT * HID) return;
    int k = t >> 7;
    int n = t & 127;
    float v = W[t];
    __nv_bfloat16 h = __float2bfloat16(v);
    __nv_bfloat16 l = __float2bfloat16(v - __bfloat162float(h));
    g_Bh[n * NFEAT + k] = h;
    g_Bl[n * NFEAT + k] = l;
}
__global__ void k_prepW2(const float* __restrict__ W) {
    int t = blockIdx.x * blockDim.x + threadIdx.x;
    if (t >= HID * NCLS) return;
    int k = t >> 6;
    int n = t & 63;
    float v = W[t];
    __nv_bfloat16 h = __float2bfloat16(v);
    __nv_bfloat16 l = __float2bfloat16(v - __bfloat162float(h));
    g_B2h[n * HID + k] = h;
    g_B2l[n * HID + k] = l;
}

// ==================== GEMM1 via mma.sync bf16 split ====================
#define STRB   80
#define BUFSZ  40960
#define OFF_AL 10240
#define OFF_BH 20480
#define OFF_BL 30720
#define NCHUNK (NFEAT / 32)     // 16
#define GSMEM_BYTES (2 * BUFSZ)

extern __shared__ __align__(128) unsigned char s_dyn[];

__global__ void __launch_bounds__(256, 2) k_gemm1_mma(const float* __restrict__ X, int N) {
    uint32_t sb = smem_u32(s_dyn);
    int tid  = threadIdx.x;
    int wid  = tid >> 5;
    int lane = tid & 31;
    int warp_m = (wid & 3) * 32;
    int warp_n = (wid >> 2) * 64;
    int rowBase = blockIdx.x * 128;

    float acc[2][8][4];
    #pragma unroll
    for (int mt = 0; mt < 2; mt++)
        #pragma unroll
        for (int nt = 0; nt < 8; nt++)
            #pragma unroll
            for (int j = 0; j < 4; j++) acc[mt][nt][j] = 0.0f;

    float4 xs[4];
    int xrow = tid >> 3;
    int xseg = tid & 7;
    int bn   = tid >> 2;
    int bseg = tid & 3;

    #define LOAD_X(c)                                                          \
        {                                                                      \
            _Pragma("unroll")                                                  \
            for (int i = 0; i < 4; i++) {                                      \
                int row = xrow + 32 * i;                                       \
                int grow = rowBase + row;                                      \
                if (grow > N - 1) grow = N - 1;                                \
                xs[i] = *(const float4*)(X + (size_t)grow * NFEAT + (c) * 32 + xseg * 4); \
            }                                                                  \
        }
    #define CP_B(c, b)                                                         \
        {                                                                      \
            _Pragma("unroll")                                                  \
            for (int i = 0; i < 2; i++) {                                      \
                int n = bn + 64 * i;                                           \
                uint32_t dst = sb + (b) * BUFSZ + OFF_BH + n * STRB + bseg * 16; \
                cp16(dst, g_Bh + (size_t)n * NFEAT + (c) * 32 + bseg * 8);      \
                cp16(dst + (OFF_BL - OFF_BH),                                   \
                     g_Bl + (size_t)n * NFEAT + (c) * 32 + bseg * 8);           \
            }                                                                  \
        }
    #define STORE_A(b)                                                         \
        {                                                                      \
            unsigned char* base = s_dyn + (b) * BUFSZ;                         \
            _Pragma("unroll")                                                  \
            for (int i = 0; i < 4; i++) {                                      \
                int row = xrow + 32 * i;                                       \
                float f[4] = {xs[i].x, xs[i].y, xs[i].z, xs[i].w};             \
                uint32_t hi[2], lo[2];                                         \
                _Pragma("unroll")                                              \
                for (int j = 0; j < 2; j++) {                                  \
                    __nv_bfloat16 ha = __float2bfloat16(f[2*j]);               \
                    __nv_bfloat16 hb = __float2bfloat16(f[2*j+1]);             \
                    __nv_bfloat162 hp; hp.x = ha; hp.y = hb;                   \
                    __nv_bfloat162 lp = __floats2bfloat162_rn(                 \
                        f[2*j]   - __bfloat162float(ha),                       \
                        f[2*j+1] - __bfloat162float(hb));                      \
                    hi[j] = *(uint32_t*)&hp;                                   \
                    lo[j] = *(uint32_t*)&lp;                                   \
                }                                                              \
                uint32_t off = row * STRB + xseg * 8;                          \
                *(uint2*)(base + off)          = make_uint2(hi[0], hi[1]);     \
                *(uint2*)(base + OFF_AL + off) = make_uint2(lo[0], lo[1]);     \
            }                                                                  \
        }

    CP_B(0, 0); CP_COMMIT();
    LOAD_X(0);
    STORE_A(0);
    CP_WAIT0();
    __syncthreads();

    uint32_t aRowOff = (warp_m + (lane & 15)) * STRB + ((lane & 16) ? 16 : 0);
    uint32_t bRowSel = (lane & 7) + ((lane & 16) ? 8 : 0);
    uint32_t bKoff   = (lane & 8) ? 16 : 0;

    #pragma unroll 1
    for (int c = 0; c < NCHUNK; c++) {
        int cur = c & 1;
        if (c + 1 < NCHUNK) {
            CP_B(c + 1, cur ^ 1); CP_COMMIT();
            LOAD_X(c + 1);
        }

        uint32_t base = sb + cur * BUFSZ;
        #pragma unroll
        for (int ka = 0; ka < 2; ka++) {
            uint32_t k0b = ka * 32;

            uint32_t ah[2][4], al[2][4];
            #pragma unroll
            for (int mt = 0; mt < 2; mt++) {
                uint32_t aaddr = base + aRowOff + mt * (16 * STRB) + k0b;
                ldm_x4(ah[mt][0], ah[mt][1], ah[mt][2], ah[mt][3], aaddr);
                ldm_x4(al[mt][0], al[mt][1], al[mt][2], al[mt][3], aaddr + OFF_AL);
            }

            uint32_t bh[8][2], bl[8][2];
            #pragma unroll
            for (int np = 0; np < 4; np++) {
                uint32_t brow = warp_n + np * 16 + bRowSel;
                uint32_t baddr = base + OFF_BH + brow * STRB + k0b + bKoff;
                ldm_x4(bh[2*np][0], bh[2*np][1], bh[2*np+1][0], bh[2*np+1][1], baddr);
                ldm_x4(bl[2*np][0], bl[2*np][1], bl[2*np+1][0], bl[2*np+1][1],
                       baddr + (OFF_BL - OFF_BH));
            }

            #pragma unroll
            for (int mt = 0; mt < 2; mt++)
                #pragma unroll
                for (int nt = 0; nt < 8; nt++) {
                    mma_bf16(acc[mt][nt][0], acc[mt][nt][1], acc[mt][nt][2], acc[mt][nt][3],
                             ah[mt][0], ah[mt][1], ah[mt][2], ah[mt][3],
                             bh[nt][0], bh[nt][1]);
                    mma_bf16(acc[mt][nt][0], acc[mt][nt][1], acc[mt][nt][2], acc[mt][nt][3],
                             ah[mt][0], ah[mt][1], ah[mt][2], ah[mt][3],
                             bl[nt][0], bl[nt][1]);
                    mma_bf16(acc[mt][nt][0], acc[mt][nt][1], acc[mt][nt][2], acc[mt][nt][3],
                             al[mt][0], al[mt][1], al[mt][2], al[mt][3],
                             bh[nt][0], bh[nt][1]);
                }
        }

        if (c + 1 < NCHUNK) {
            STORE_A(cur ^ 1);
            CP_WAIT0();
        }
        __syncthreads();
    }

    int r0 = rowBase + warp_m + (lane >> 2);
    int cc = warp_n + 2 * (lane & 3);
    #pragma unroll
    for (int mt = 0; mt < 2; mt++) {
        int ra = r0 + mt * 16;
        int rb = ra + 8;
        #pragma unroll
        for (int nt = 0; nt < 8; nt++) {
            int col = cc + nt * 8;
            if (ra < N)
                *(float2*)(g_H1 + (size_t)ra * HID + col) =
                    make_float2(acc[mt][nt][0], acc[mt][nt][1]);
            if (rb < N)
                *(float2*)(g_H1 + (size_t)rb * HID + col) =
                    make_float2(acc[mt][nt][2], acc[mt][nt][3]);
        }
    }
    #undef LOAD_X
    #undef CP_B
    #undef STORE_A
}

// ==================== layer-1 aggregation (warp per node) ====================
__global__ __launch_bounds__(256) void k_agg1(const float* __restrict__ b1, int N) {
    int w    = (blockIdx.x * blockDim.x + threadIdx.x) >> 5;
    int lane = threadIdx.x & 31;
    if (w >= N) return;

    float di = g_dinv[w];
    float s2 = di * di;
    float4 acc = ((const float4*)b1)[lane];
    float4 h   = *((const float4*)(g_H1 + (size_t)w * HID) + lane);
    acc.x += s2 * h.x; acc.y += s2 * h.y; acc.z += s2 * h.z; acc.w += s2 * h.w;

    int e   = g_rs[w];
    int end = g_rs[w + 1];
    for (; e + 1 < end; e += 2) {
        int2 p0 = g_csr[e];
        int2 p1 = g_csr[e + 1];
        float n0 = __int_as_float(p0.y);
        float n1 = __int_as_float(p1.y);
        float4 v0 = __ldg((const float4*)(g_H1 + (size_t)p0.x * HID) + lane);
        float4 v1 = __ldg((const float4*)(g_H1 + (size_t)p1.x * HID) + lane);
        acc.x += n0 * v0.x; acc.y += n0 * v0.y; acc.z += n0 * v0.z; acc.w += n0 * v0.w;
        acc.x += n1 * v1.x; acc.y += n1 * v1.y; acc.z += n1 * v1.z; acc.w += n1 * v1.w;
    }
    if (e < end) {
        int2 p0 = g_csr[e];
        float n0 = __int_as_float(p0.y);
        float4 v0 = __ldg((const float4*)(g_H1 + (size_t)p0.x * HID) + lane);
        acc.x += n0 * v0.x; acc.y += n0 * v0.y; acc.z += n0 * v0.z; acc.w += n0 * v0.w;
    }

    acc.x = fmaxf(acc.x, 0.f); acc.y = fmaxf(acc.y, 0.f);
    acc.z = fmaxf(acc.z, 0.f); acc.w = fmaxf(acc.w, 0.f);
    *((float4*)(g_agg1 + (size_t)w * HID) + lane) = acc;
}

// ==================== GEMM2 via mma.sync bf16 split (128x64 tile) ====================
#define BUF2SZ  30720
#define OFF2_AL 10240
#define OFF2_BH 20480
#define OFF2_BL 25600
#define NCHUNK2 (HID / 32)      // 4
#define G2SMEM_BYTES (2 * BUF2SZ)

__global__ void __launch_bounds__(256) k_gemm2_mma(int N) {
    uint32_t sb = smem_u32(s_dyn);
    int tid  = threadIdx.x;
    int wid  = tid >> 5;
    int lane = tid & 31;
    int warp_m = (wid & 3) * 32;
    int warp_n = (wid >> 2) * 32;
    int rowBase = blockIdx.x * 128;

    float acc[2][4][4];
    #pragma unroll
    for (int mt = 0; mt < 2; mt++)
        #pragma unroll
        for (int nt = 0; nt < 4; nt++)
            #pragma unroll
            for (int j = 0; j < 4; j++) acc[mt][nt][j] = 0.0f;

    float4 xs[4];
    int xrow = tid >> 3;
    int xseg = tid & 7;
    int bn   = tid >> 2;
    int bseg = tid & 3;

    #define LOAD_X2(c)                                                         \
        {                                                                      \
            _Pragma("unroll")                                                  \
            for (int i = 0; i < 4; i++) {                                      \
                int row = xrow + 32 * i;                                       \
                int grow = rowBase + row;                                      \
                if (grow > N - 1) grow = N - 1;                                \
                xs[i] = *(const float4*)(g_agg1 + (size_t)grow * HID + (c) * 32 + xseg * 4); \
            }                                                                  \
        }
    #define CP_B2(c, b)                                                        \
        {                                                                      \
            uint32_t dst = sb + (b) * BUF2SZ + OFF2_BH + bn * STRB + bseg * 16; \
            cp16(dst, g_B2h + (size_t)bn * HID + (c) * 32 + bseg * 8);          \
            cp16(dst + (OFF2_BL - OFF2_BH),                                     \
                 g_B2l + (size_t)bn * HID + (c) * 32 + bseg * 8);               \
        }
    #define STORE_A2(b)                                                        \
        {                                                                      \
            unsigned char* base = s_dyn + (b) * BUF2SZ;                        \
            _Pragma("unroll")                                                  \
            for (int i = 0; i < 4; i++) {                                      \
                int row = xrow + 32 * i;                                       \
                float f[4] = {xs[i].x, xs[i].y, xs[i].z, xs[i].w};             \
                uint32_t hi[2], lo[2];                                         \
                _Pragma("unroll")                                              \
                for (int j = 0; j < 2; j++) {                                  \
                    __nv_bfloat16 ha = __float2bfloat16(f[2*j]);               \
                    __nv_bfloat16 hb = __float2bfloat16(f[2*j+1]);             \
                    __nv_bfloat162 hp; hp.x = ha; hp.y = hb;                   \
                    __nv_bfloat162 lp = __floats2bfloat162_rn(                 \
                        f[2*j]   - __bfloat162float(ha),                       \
                        f[2*j+1] - __bfloat162float(hb));                      \
                    hi[j] = *(uint32_t*)&hp;                                   \
                    lo[j] = *(uint32_t*)&lp;                                   \
                }                                                              \
                uint32_t off = row * STRB + xseg * 8;                          \
                *(uint2*)(base + off)           = make_uint2(hi[0], hi[1]);    \
                *(uint2*)(base + OFF2_AL + off) = make_uint2(lo[0], lo[1]);    \
            }                                                                  \
        }

    CP_B2(0, 0); CP_COMMIT();
    LOAD_X2(0);
    STORE_A2(0);
    CP_WAIT0();
    __syncthreads();

    uint32_t aRowOff = (warp_m + (lane & 15)) * STRB + ((lane & 16) ? 16 : 0);
    uint32_t bRowSel = (lane & 7) + ((lane & 16) ? 8 : 0);
    uint32_t bKoff   = (lane & 8) ? 16 : 0;

    #pragma unroll 1
    for (int c = 0; c < NCHUNK2; c++) {
        int cur = c & 1;
        if (c + 1 < NCHUNK2) {
            CP_B2(c + 1, cur ^ 1); CP_COMMIT();
            LOAD_X2(c + 1);
        }

        uint32_t base = sb + cur * BUF2SZ;
        #pragma unroll
        for (int ka = 0; ka < 2; ka++) {
            uint32_t k0b = ka * 32;

            uint32_t ah[2][4], al[2][4];
            #pragma unroll
            for (int mt = 0; mt < 2; mt++) {
                uint32_t aaddr = base + aRowOff + mt * (16 * STRB) + k0b;
                ldm_x4(ah[mt][0], ah[mt][1], ah[mt][2], ah[mt][3], aaddr);
                ldm_x4(al[mt][0], al[mt][1], al[mt][2], al[mt][3], aaddr + OFF2_AL);
            }

            uint32_t bh[4][2], bl[4][2];
            #pragma unroll
            for (int np = 0; np < 2; np++) {
                uint32_t brow = warp_n + np * 16 + bRowSel;
                uint32_t baddr = base + OFF2_BH + brow * STRB + k0b + bKoff;
                ldm_x4(bh[2*np][0], bh[2*np][1], bh[2*np+1][0], bh[2*np+1][1], baddr);
                ldm_x4(bl[2*np][0], bl[2*np][1], bl[2*np+1][0], bl[2*np+1][1],
                       baddr + (OFF2_BL - OFF2_BH));
            }

            #pragma unroll
            for (int mt = 0; mt < 2; mt++)
                #pragma unroll
                for (int nt = 0; nt < 4; nt++) {
                    mma_bf16(acc[mt][nt][0], acc[mt][nt][1], acc[mt][nt][2], acc[mt][nt][3],
                             ah[mt][0], ah[mt][1], ah[mt][2], ah[mt][3],
                             bh[nt][0], bh[nt][1]);
                    mma_bf16(acc[mt][nt][0], acc[mt][nt][1], acc[mt][nt][2], acc[mt][nt][3],
                             ah[mt][0], ah[mt][1], ah[mt][2], ah[mt][3],
                             bl[nt][0], bl[nt][1]);
                    mma_bf16(acc[mt][nt][0], acc[mt][nt][1], acc[mt][nt][2], acc[mt][nt][3],
                             al[mt][0], al[mt][1], al[mt][2], al[mt][3],
                             bh[nt][0], bh[nt][1]);
                }
        }

        if (c + 1 < NCHUNK2) {
            STORE_A2(cur ^ 1);
            CP_WAIT0();
        }
        __syncthreads();
    }

    int r0 = rowBase + warp_m + (lane >> 2);
    int cc = warp_n + 2 * (lane & 3);
    #pragma unroll
    for (int mt = 0; mt < 2; mt++) {
        int ra = r0 + mt * 16;
        int rb = ra + 8;
        #pragma unroll
        for (int nt = 0; nt < 4; nt++) {
            int col = cc + nt * 8;
            if (ra < N)
                *(float2*)(g_H2 + (size_t)ra * NCLS + col) =
                    make_float2(acc[mt][nt][0], acc[mt][nt][1]);
            if (rb < N)
                *(float2*)(g_H2 + (size_t)rb * NCLS + col) =
                    make_float2(acc[mt][nt][2], acc[mt][nt][3]);
        }
    }
    #undef LOAD_X2
    #undef CP_B2
    #undef STORE_A2
}

// ==================== layer-2 aggregation (16 lanes per node) ====================
__global__ __launch_bounds__(256) void k_agg2(const float* __restrict__ b2,
                                              float* __restrict__ out, int N) {
    int t = blockIdx.x * blockDim.x + threadIdx.x;
    int i = t >> 4;
    int c = t & 15;
    if (i >= N) return;

    float di = g_dinv[i];
    float s2 = di * di;
    float4 acc = ((const float4*)b2)[c];
    float4 h   = *((const float4*)(g_H2 + (size_t)i * NCLS) + c);
    acc.x += s2 * h.x; acc.y += s2 * h.y; acc.z += s2 * h.z; acc.w += s2 * h.w;

    int e   = g_rs[i];
    int end = g_rs[i + 1];
    for (; e + 1 < end; e += 2) {
        int2 p0 = g_csr[e];
        int2 p1 = g_csr[e + 1];
        float n0 = __int_as_float(p0.y);
        float n1 = __int_as_float(p1.y);
        float4 v0 = __ldg((const float4*)(g_H2 + (size_t)p0.x * NCLS) + c);
        float4 v1 = __ldg((const float4*)(g_H2 + (size_t)p1.x * NCLS) + c);
        acc.x += n0 * v0.x; acc.y += n0 * v0.y; acc.z += n0 * v0.z; acc.w += n0 * v0.w;
        acc.x += n1 * v1.x; acc.y += n1 * v1.y; acc.z += n1 * v1.z; acc.w += n1 * v1.w;
    }
    if (e < end) {
        int2 p0 = g_csr[e];
        float n0 = __int_as_float(p0.y);
        float4 v0 = __ldg((const float4*)(g_H2 + (size_t)p0.x * NCLS) + c);
        acc.x += n0 * v0.x; acc.y += n0 * v0.y; acc.z += n0 * v0.z; acc.w += n0 * v0.w;
    }

    *((float4*)(out + (size_t)i * NCLS) + c) = acc;
}

// ==================== launch ====================
struct AuxObjs {
    cudaStream_t s1;
    cudaEvent_t  e0, e1;
    AuxObjs() {
        cudaStreamCreateWithFlags(&s1, cudaStreamNonBlocking);
        cudaEventCreateWithFlags(&e0, cudaEventDisableTiming);
        cudaEventCreateWithFlags(&e1, cudaEventDisableTiming);
    }
};

extern "C" void kernel_launch(void* const* d_in, const int* in_sizes, int n_in,
                              void* d_out, int out_size) {
    static AuxObjs aux;

    const float* x  = (const float*)d_in[0];
    const int*   ei = (const int*)  d_in[1];
    const float* W1 = (const float*)d_in[2];
    const float* b1 = (const float*)d_in[3];
    const float* W2 = (const float*)d_in[4];
    const float* b2 = (const float*)d_in[5];
    float* out = (float*)d_out;

    int N = in_sizes[0] / NFEAT;   // 50000
    int E = in_sizes[1] / 2;       // 640000
    int nb = (N + 255) / 256;

    cudaFuncSetAttribute(k_gemm1_mma, cudaFuncAttributeMaxDynamicSharedMemorySize,
                         GSMEM_BYTES);
    cudaFuncSetAttribute(k_gemm2_mma, cudaFuncAttributeMaxDynamicSharedMemorySize,
                         G2SMEM_BYTES);

    // Fork CSR branch onto s1.
    cudaEventRecord(aux.e0, 0);
    cudaStreamWaitEvent(aux.s1, aux.e0, 0);

    k_cnt_init<<<(N + 255) / 256, 256, 0, aux.s1>>>(N);          // launch 1
    k_cnt_acc <<<(E + 255) / 256, 256, 0, aux.s1>>>(ei, E);      // launch 2
    k_prepW   <<<(NFEAT * HID + 255) / 256, 256>>>(W1);          // launch 3 (main)
    k_gemm1_mma<<<(N + 127) / 128, 256, GSMEM_BYTES>>>(x, N);    // launch 4 (profiled)
    k_scan1   <<<nb, 256, 0, aux.s1>>>(N);                       // launch 5
    k_scan2   <<<1, 256, 0, aux.s1>>>(nb, N, E);                 // launch 6
    k_scan3   <<<nb, 256, 0, aux.s1>>>(N);                       // launch 7
    k_scatter <<<(E + 255) / 256, 256, 0, aux.s1>>>(ei, E);      // launch 8
    k_prepW2  <<<(HID * NCLS + 255) / 256, 256>>>(W2);           // launch 9 (main)
    cudaEventRecord(aux.e1, aux.s1);
    cudaStreamWaitEvent(0, aux.e1, 0);

    k_agg1     <<<(N * 32 + 255) / 256, 256>>>(b1, N);           // launch 10
    k_gemm2_mma<<<(N + 127) / 128, 256, G2SMEM_BYTES>>>(N);      // launch 11
    k_agg2     <<<(N * 16 + 255) / 256, 256>>>(b2, out, N);      // launch 12
}

// round 8
// speedup vs baseline: 1.3029x; 1.0296x over previous
#include <cuda_runtime.h>
#include <cuda_bf16.h>
#include <cuda_fp16.h>
#include <cstdint>

#define NFEAT 512
#define HID   128
#define NCLS  64
#define NMAX  50048
#define EMAX  640000

// ---------------- device scratch ----------------
__device__ float g_dinv[NMAX];
__device__ int   g_cnt [NMAX];
__device__ int   g_excl[NMAX];
__device__ int   g_bsum[256];
__device__ int   g_boff[256];
__device__ int   g_rs  [NMAX + 1];
__device__ int   g_cur [NMAX];
__device__ int2  g_csr [EMAX];
__device__ float g_H1  [(size_t)NMAX * HID];
__device__ __half g_H1h[(size_t)NMAX * HID];     // fp16 copy for gather
__device__ float g_agg1[(size_t)NMAX * HID];
__device__ float g_H2  [(size_t)NMAX * NCLS];
__device__ __half g_H2h[(size_t)NMAX * NCLS];    // fp16 copy for gather
__device__ __nv_bfloat16 g_Bh[HID * NFEAT];
__device__ __nv_bfloat16 g_Bl[HID * NFEAT];
__device__ __nv_bfloat16 g_B2h[NCLS * HID];
__device__ __nv_bfloat16 g_B2l[NCLS * HID];

// ==================== helpers ====================
__device__ __forceinline__ uint32_t smem_u32(const void* p) {
    uint32_t a;
    asm("{ .reg .u64 t; cvta.to.shared.u64 t, %1; cvt.u32.u64 %0, t; }"
        : "=r"(a) : "l"(p));
    return a;
}
__device__ __forceinline__ void ldm_x4(uint32_t& r0, uint32_t& r1,
                                       uint32_t& r2, uint32_t& r3, uint32_t addr) {
    asm volatile("ldmatrix.sync.aligned.m8n8.x4.shared.b16 {%0,%1,%2,%3}, [%4];"
                 : "=r"(r0), "=r"(r1), "=r"(r2), "=r"(r3) : "r"(addr));
}
__device__ __forceinline__ void mma_bf16(float& d0, float& d1, float& d2, float& d3,
                                         uint32_t a0, uint32_t a1, uint32_t a2, uint32_t a3,
                                         uint32_t b0, uint32_t b1) {
    asm volatile(
        "mma.sync.aligned.m16n8k16.row.col.f32.bf16.bf16.f32 "
        "{%0,%1,%2,%3}, {%4,%5,%6,%7}, {%8,%9}, {%0,%1,%2,%3};"
        : "+f"(d0), "+f"(d1), "+f"(d2), "+f"(d3)
        : "r"(a0), "r"(a1), "r"(a2), "r"(a3), "r"(b0), "r"(b1));
}
__device__ __forceinline__ void cp16(uint32_t dst, const void* src) {
    asm volatile("cp.async.cg.shared.global [%0], [%1], 16;" :: "r"(dst), "l"(src));
}
#define CP_COMMIT() asm volatile("cp.async.commit_group;" ::: "memory")
#define CP_WAIT0()  asm volatile("cp.async.wait_group 0;" ::: "memory")

// ==================== CSR build ====================
__global__ void k_cnt_init(int N) {
    int i = blockIdx.x * blockDim.x + threadIdx.x;
    if (i < N) g_cnt[i] = 0;
}
__global__ void k_cnt_acc(const int* __restrict__ ei, int E) {
    int e = blockIdx.x * blockDim.x + threadIdx.x;
    if (e < E) atomicAdd(&g_cnt[ei[E + e]], 1);
}
__global__ void k_scan1(int N) {
    __shared__ int sh[256];
    int i = blockIdx.x * 256 + threadIdx.x;
    int v = (i < N) ? g_cnt[i] : 0;
    if (i < N) g_dinv[i] = rsqrtf((float)(v + 1));
    sh[threadIdx.x] = v;
    __syncthreads();
    #pragma unroll
    for (int off = 1; off < 256; off <<= 1) {
        int t = (threadIdx.x >= off) ? sh[threadIdx.x - off] : 0;
        __syncthreads();
        sh[threadIdx.x] += t;
        __syncthreads();
    }
    if (i < N) g_excl[i] = sh[threadIdx.x] - v;
    if (threadIdx.x == 255) g_bsum[blockIdx.x] = sh[255];
}
__global__ void k_scan2(int nb, int N, int E) {
    __shared__ int sh[256];
    int v = (threadIdx.x < nb) ? g_bsum[threadIdx.x] : 0;
    sh[threadIdx.x] = v;
    __syncthreads();
    #pragma unroll
    for (int off = 1; off < 256; off <<= 1) {
        int t = (threadIdx.x >= off) ? sh[threadIdx.x - off] : 0;
        __syncthreads();
        sh[threadIdx.x] += t;
        __syncthreads();
    }
    if (threadIdx.x < nb) g_boff[threadIdx.x] = sh[threadIdx.x] - v;
    if (threadIdx.x == 0) g_rs[N] = E;
}
__global__ void k_scan3(int N) {
    int i = blockIdx.x * blockDim.x + threadIdx.x;
    if (i < N) {
        int r = g_excl[i] + g_boff[i >> 8];
        g_rs[i]  = r;
        g_cur[i] = r;
    }
}
__global__ void k_scatter(const int* __restrict__ ei, int E) {
    int e = blockIdx.x * blockDim.x + threadIdx.x;
    if (e >= E) return;
    int s = ei[e];
    int d = ei[E + e];
    int pos = atomicAdd(&g_cur[d], 1);
    g_csr[pos] = make_int2(s, __float_as_int(g_dinv[s] * g_dinv[d]));
}

// ==================== weight prep (merged W1 + W2) ====================
__global__ void k_prep(const float* __restrict__ W1, const float* __restrict__ W2) {
    int t = blockIdx.x * blockDim.x + threadIdx.x;
    if (t < NFEAT * HID) {
        int k = t >> 7;
        int n = t & 127;
        float v = W1[t];
        __nv_bfloat16 h = __float2bfloat16(v);
        __nv_bfloat16 l = __float2bfloat16(v - __bfloat162float(h));
        g_Bh[n * NFEAT + k] = h;
        g_Bl[n * NFEAT + k] = l;
    } else if (t < NFEAT * HID + HID * NCLS) {
        int u = t - NFEAT * HID;
        int k = u >> 6;
        int n = u & 63;
        float v = W2[u];
        __nv_bfloat16 h = __float2bfloat16(v);
        __nv_bfloat16 l = __float2bfloat16(v - __bfloat162float(h));
        g_B2h[n * HID + k] = h;
        g_B2l[n * HID + k] = l;
    }
}

// ==================== GEMM1 via mma.sync bf16 split ====================
#define STRB   80
#define BUFSZ  40960
#define OFF_AL 10240
#define OFF_BH 20480
#define OFF_BL 30720
#define NCHUNK (NFEAT / 32)     // 16
#define GSMEM_BYTES (2 * BUFSZ)

extern __shared__ __align__(128) unsigned char s_dyn[];

__global__ void __launch_bounds__(256, 2) k_gemm1_mma(const float* __restrict__ X, int N) {
    uint32_t sb = smem_u32(s_dyn);
    int tid  = threadIdx.x;
    int wid  = tid >> 5;
    int lane = tid & 31;
    int warp_m = (wid & 3) * 32;
    int warp_n = (wid >> 2) * 64;
    int rowBase = blockIdx.x * 128;

    float acc[2][8][4];
    #pragma unroll
    for (int mt = 0; mt < 2; mt++)
        #pragma unroll
        for (int nt = 0; nt < 8; nt++)
            #pragma unroll
            for (int j = 0; j < 4; j++) acc[mt][nt][j] = 0.0f;

    float4 xs[4];
    int xrow = tid >> 3;
    int xseg = tid & 7;
    int bn   = tid >> 2;
    int bseg = tid & 3;

    #define LOAD_X(c)                                                          \
        {                                                                      \
            _Pragma("unroll")                                                  \
            for (int i = 0; i < 4; i++) {                                      \
                int row = xrow + 32 * i;                                       \
                int grow = rowBase + row;                                      \
                if (grow > N - 1) grow = N - 1;                                \
                xs[i] = *(const float4*)(X + (size_t)grow * NFEAT + (c) * 32 + xseg * 4); \
            }                                                                  \
        }
    #define CP_B(c, b)                                                         \
        {                                                                      \
            _Pragma("unroll")                                                  \
            for (int i = 0; i < 2; i++) {                                      \
                int n = bn + 64 * i;                                           \
                uint32_t dst = sb + (b) * BUFSZ + OFF_BH + n * STRB + bseg * 16; \
                cp16(dst, g_Bh + (size_t)n * NFEAT + (c) * 32 + bseg * 8);      \
                cp16(dst + (OFF_BL - OFF_BH),                                   \
                     g_Bl + (size_t)n * NFEAT + (c) * 32 + bseg * 8);           \
            }                                                                  \
        }
    #define STORE_A(b)                                                         \
        {                                                                      \
            unsigned char* base = s_dyn + (b) * BUFSZ;                         \
            _Pragma("unroll")                                                  \
            for (int i = 0; i < 4; i++) {                                      \
                int row = xrow + 32 * i;                                       \
                float f[4] = {xs[i].x, xs[i].y, xs[i].z, xs[i].w};             \
                uint32_t hi[2], lo[2];                                         \
                _Pragma("unroll")                                              \
                for (int j = 0; j < 2; j++) {                                  \
                    __nv_bfloat16 ha = __float2bfloat16(f[2*j]);               \
                    __nv_bfloat16 hb = __float2bfloat16(f[2*j+1]);             \
                    __nv_bfloat162 hp; hp.x = ha; hp.y = hb;                   \
                    __nv_bfloat162 lp = __floats2bfloat162_rn(                 \
                        f[2*j]   - __bfloat162float(ha),                       \
                        f[2*j+1] - __bfloat162float(hb));                      \
                    hi[j] = *(uint32_t*)&hp;                                   \
                    lo[j] = *(uint32_t*)&lp;                                   \
                }                                                              \
                uint32_t off = row * STRB + xseg * 8;                          \
                *(uint2*)(base + off)          = make_uint2(hi[0], hi[1]);     \
                *(uint2*)(base + OFF_AL + off) = make_uint2(lo[0], lo[1]);     \
            }                                                                  \
        }

    CP_B(0, 0); CP_COMMIT();
    LOAD_X(0);
    STORE_A(0);
    CP_WAIT0();
    __syncthreads();

    uint32_t aRowOff = (warp_m + (lane & 15)) * STRB + ((lane & 16) ? 16 : 0);
    uint32_t bRowSel = (lane & 7) + ((lane & 16) ? 8 : 0);
    uint32_t bKoff   = (lane & 8) ? 16 : 0;

    #pragma unroll 1
    for (int c = 0; c < NCHUNK; c++) {
        int cur = c & 1;
        if (c + 1 < NCHUNK) {
            CP_B(c + 1, cur ^ 1); CP_COMMIT();
            LOAD_X(c + 1);
        }

        uint32_t base = sb + cur * BUFSZ;
        #pragma unroll
        for (int ka = 0; ka < 2; ka++) {
            uint32_t k0b = ka * 32;

            uint32_t ah[2][4], al[2][4];
            #pragma unroll
            for (int mt = 0; mt < 2; mt++) {
                uint32_t aaddr = base + aRowOff + mt * (16 * STRB) + k0b;
                ldm_x4(ah[mt][0], ah[mt][1], ah[mt][2], ah[mt][3], aaddr);
                ldm_x4(al[mt][0], al[mt][1], al[mt][2], al[mt][3], aaddr + OFF_AL);
            }

            uint32_t bh[8][2], bl[8][2];
            #pragma unroll
            for (int np = 0; np < 4; np++) {
                uint32_t brow = warp_n + np * 16 + bRowSel;
                uint32_t baddr = base + OFF_BH + brow * STRB + k0b + bKoff;
                ldm_x4(bh[2*np][0], bh[2*np][1], bh[2*np+1][0], bh[2*np+1][1], baddr);
                ldm_x4(bl[2*np][0], bl[2*np][1], bl[2*np+1][0], bl[2*np+1][1],
                       baddr + (OFF_BL - OFF_BH));
            }

            #pragma unroll
            for (int mt = 0; mt < 2; mt++)
                #pragma unroll
                for (int nt = 0; nt < 8; nt++) {
                    mma_bf16(acc[mt][nt][0], acc[mt][nt][1], acc[mt][nt][2], acc[mt][nt][3],
                             ah[mt][0], ah[mt][1], ah[mt][2], ah[mt][3],
                             bh[nt][0], bh[nt][1]);
                    mma_bf16(acc[mt][nt][0], acc[mt][nt][1], acc[mt][nt][2], acc[mt][nt][3],
                             ah[mt][0], ah[mt][1], ah[mt][2], ah[mt][3],
                             bl[nt][0], bl[nt][1]);
                    mma_bf16(acc[mt][nt][0], acc[mt][nt][1], acc[mt][nt][2], acc[mt][nt][3],
                             al[mt][0], al[mt][1], al[mt][2], al[mt][3],
                             bh[nt][0], bh[nt][1]);
                }
        }

        if (c + 1 < NCHUNK) {
            STORE_A(cur ^ 1);
            CP_WAIT0();
        }
        __syncthreads();
    }

    int r0 = rowBase + warp_m + (lane >> 2);
    int cc = warp_n + 2 * (lane & 3);
    #pragma unroll
    for (int mt = 0; mt < 2; mt++) {
        int ra = r0 + mt * 16;
        int rb = ra + 8;
        #pragma unroll
        for (int nt = 0; nt < 8; nt++) {
            int col = cc + nt * 8;
            if (ra < N) {
                *(float2*)(g_H1 + (size_t)ra * HID + col) =
                    make_float2(acc[mt][nt][0], acc[mt][nt][1]);
                *(__half2*)(g_H1h + (size_t)ra * HID + col) =
                    __floats2half2_rn(acc[mt][nt][0], acc[mt][nt][1]);
            }
            if (rb < N) {
                *(float2*)(g_H1 + (size_t)rb * HID + col) =
                    make_float2(acc[mt][nt][2], acc[mt][nt][3]);
                *(__half2*)(g_H1h + (size_t)rb * HID + col) =
                    __floats2half2_rn(acc[mt][nt][2], acc[mt][nt][3]);
            }
        }
    }
    #undef LOAD_X
    #undef CP_B
    #undef STORE_A
}

// ==================== layer-1 aggregation (warp per node, fp16 gather) ====================
__global__ __launch_bounds__(256) void k_agg1(const float* __restrict__ b1, int N) {
    int w    = (blockIdx.x * blockDim.x + threadIdx.x) >> 5;
    int lane = threadIdx.x & 31;
    if (w >= N) return;

    float di = g_dinv[w];
    float s2 = di * di;
    float4 acc = ((const float4*)b1)[lane];
    float4 h   = *((const float4*)(g_H1 + (size_t)w * HID) + lane);
    acc.x += s2 * h.x; acc.y += s2 * h.y; acc.z += s2 * h.z; acc.w += s2 * h.w;

    int e   = g_rs[w];
    int end = g_rs[w + 1];
    for (; e + 1 < end; e += 2) {
        int2 p0 = g_csr[e];
        int2 p1 = g_csr[e + 1];
        float n0 = __int_as_float(p0.y);
        float n1 = __int_as_float(p1.y);
        uint2 r0 = __ldg((const uint2*)(g_H1h + (size_t)p0.x * HID) + lane);
        uint2 r1 = __ldg((const uint2*)(g_H1h + (size_t)p1.x * HID) + lane);
        float2 a0 = __half22float2(*(__half2*)&r0.x);
        float2 a1 = __half22float2(*(__half2*)&r0.y);
        float2 c0 = __half22float2(*(__half2*)&r1.x);
        float2 c1 = __half22float2(*(__half2*)&r1.y);
        acc.x += n0 * a0.x; acc.y += n0 * a0.y; acc.z += n0 * a1.x; acc.w += n0 * a1.y;
        acc.x += n1 * c0.x; acc.y += n1 * c0.y; acc.z += n1 * c1.x; acc.w += n1 * c1.y;
    }
    if (e < end) {
        int2 p0 = g_csr[e];
        float n0 = __int_as_float(p0.y);
        uint2 r0 = __ldg((const uint2*)(g_H1h + (size_t)p0.x * HID) + lane);
        float2 a0 = __half22float2(*(__half2*)&r0.x);
        float2 a1 = __half22float2(*(__half2*)&r0.y);
        acc.x += n0 * a0.x; acc.y += n0 * a0.y; acc.z += n0 * a1.x; acc.w += n0 * a1.y;
    }

    acc.x = fmaxf(acc.x, 0.f); acc.y = fmaxf(acc.y, 0.f);
    acc.z = fmaxf(acc.z, 0.f); acc.w = fmaxf(acc.w, 0.f);
    *((float4*)(g_agg1 + (size_t)w * HID) + lane) = acc;
}

// ==================== GEMM2 via mma.sync bf16 split (128x64 tile) ====================
#define BUF2SZ  30720
#define OFF2_AL 10240
#define OFF2_BH 20480
#define OFF2_BL 25600
#define NCHUNK2 (HID / 32)      // 4
#define G2SMEM_BYTES (2 * BUF2SZ)

__global__ void __launch_bounds__(256) k_gemm2_mma(int N) {
    uint32_t sb = smem_u32(s_dyn);
    int tid  = threadIdx.x;
    int wid  = tid >> 5;
    int lane = tid & 31;
    int warp_m = (wid & 3) * 32;
    int warp_n = (wid >> 2) * 32;
    int rowBase = blockIdx.x * 128;

    float acc[2][4][4];
    #pragma unroll
    for (int mt = 0; mt < 2; mt++)
        #pragma unroll
        for (int nt = 0; nt < 4; nt++)
            #pragma unroll
            for (int j = 0; j < 4; j++) acc[mt][nt][j] = 0.0f;

    float4 xs[4];
    int xrow = tid >> 3;
    int xseg = tid & 7;
    int bn   = tid >> 2;
    int bseg = tid & 3;

    #define LOAD_X2(c)                                                         \
        {                                                                      \
            _Pragma("unroll")                                                  \
            for (int i = 0; i < 4; i++) {                                      \
                int row = xrow + 32 * i;                                       \
                int grow = rowBase + row;                                      \
                if (grow > N - 1) grow = N - 1;                                \
                xs[i] = *(const float4*)(g_agg1 + (size_t)grow * HID + (c) * 32 + xseg * 4); \
            }                                                                  \
        }
    #define CP_B2(c, b)                                                        \
        {                                                                      \
            uint32_t dst = sb + (b) * BUF2SZ + OFF2_BH + bn * STRB + bseg * 16; \
            cp16(dst, g_B2h + (size_t)bn * HID + (c) * 32 + bseg * 8);          \
            cp16(dst + (OFF2_BL - OFF2_BH),                                     \
                 g_B2l + (size_t)bn * HID + (c) * 32 + bseg * 8);               \
        }
    #define STORE_A2(b)                                                        \
        {                                                                      \
            unsigned char* base = s_dyn + (b) * BUF2SZ;                        \
            _Pragma("unroll")                                                  \
            for (int i = 0; i < 4; i++) {                                      \
                int row = xrow + 32 * i;                                       \
                float f[4] = {xs[i].x, xs[i].y, xs[i].z, xs[i].w};             \
                uint32_t hi[2], lo[2];                                         \
                _Pragma("unroll")                                              \
                for (int j = 0; j < 2; j++) {                                  \
                    __nv_bfloat16 ha = __float2bfloat16(f[2*j]);               \
                    __nv_bfloat16 hb = __float2bfloat16(f[2*j+1]);             \
                    __nv_bfloat162 hp; hp.x = ha; hp.y = hb;                   \
                    __nv_bfloat162 lp = __floats2bfloat162_rn(                 \
                        f[2*j]   - __bfloat162float(ha),                       \
                        f[2*j+1] - __bfloat162float(hb));                      \
                    hi[j] = *(uint32_t*)&hp;                                   \
                    lo[j] = *(uint32_t*)&lp;                                   \
                }                                                              \
                uint32_t off = row * STRB + xseg * 8;                          \
                *(uint2*)(base + off)           = make_uint2(hi[0], hi[1]);    \
                *(uint2*)(base + OFF2_AL + off) = make_uint2(lo[0], lo[1]);    \
            }                                                                  \
        }

    CP_B2(0, 0); CP_COMMIT();
    LOAD_X2(0);
    STORE_A2(0);
    CP_WAIT0();
    __syncthreads();

    uint32_t aRowOff = (warp_m + (lane & 15)) * STRB + ((lane & 16) ? 16 : 0);
    uint32_t bRowSel = (lane & 7) + ((lane & 16) ? 8 : 0);
    uint32_t bKoff   = (lane & 8) ? 16 : 0;

    #pragma unroll 1
    for (int c = 0; c < NCHUNK2; c++) {
        int cur = c & 1;
        if (c + 1 < NCHUNK2) {
            CP_B2(c + 1, cur ^ 1); CP_COMMIT();
            LOAD_X2(c + 1);
        }

        uint32_t base = sb + cur * BUF2SZ;
        #pragma unroll
        for (int ka = 0; ka < 2; ka++) {
            uint32_t k0b = ka * 32;

            uint32_t ah[2][4], al[2][4];
            #pragma unroll
            for (int mt = 0; mt < 2; mt++) {
                uint32_t aaddr = base + aRowOff + mt * (16 * STRB) + k0b;
                ldm_x4(ah[mt][0], ah[mt][1], ah[mt][2], ah[mt][3], aaddr);
                ldm_x4(al[mt][0], al[mt][1], al[mt][2], al[mt][3], aaddr + OFF2_AL);
            }

            uint32_t bh[4][2], bl[4][2];
            #pragma unroll
            for (int np = 0; np < 2; np++) {
                uint32_t brow = warp_n + np * 16 + bRowSel;
                uint32_t baddr = base + OFF2_BH + brow * STRB + k0b + bKoff;
                ldm_x4(bh[2*np][0], bh[2*np][1], bh[2*np+1][0], bh[2*np+1][1], baddr);
                ldm_x4(bl[2*np][0], bl[2*np][1], bl[2*np+1][0], bl[2*np+1][1],
                       baddr + (OFF2_BL - OFF2_BH));
            }

            #pragma unroll
            for (int mt = 0; mt < 2; mt++)
                #pragma unroll
                for (int nt = 0; nt < 4; nt++) {
                    mma_bf16(acc[mt][nt][0], acc[mt][nt][1], acc[mt][nt][2], acc[mt][nt][3],
                             ah[mt][0], ah[mt][1], ah[mt][2], ah[mt][3],
                             bh[nt][0], bh[nt][1]);
                    mma_bf16(acc[mt][nt][0], acc[mt][nt][1], acc[mt][nt][2], acc[mt][nt][3],
                             ah[mt][0], ah[mt][1], ah[mt][2], ah[mt][3],
                             bl[nt][0], bl[nt][1]);
                    mma_bf16(acc[mt][nt][0], acc[mt][nt][1], acc[mt][nt][2], acc[mt][nt][3],
                             al[mt][0], al[mt][1], al[mt][2], al[mt][3],
                             bh[nt][0], bh[nt][1]);
                }
        }

        if (c + 1 < NCHUNK2) {
            STORE_A2(cur ^ 1);
            CP_WAIT0();
        }
        __syncthreads();
    }

    int r0 = rowBase + warp_m + (lane >> 2);
    int cc = warp_n + 2 * (lane & 3);
    #pragma unroll
    for (int mt = 0; mt < 2; mt++) {
        int ra = r0 + mt * 16;
        int rb = ra + 8;
        #pragma unroll
        for (int nt = 0; nt < 4; nt++) {
            int col = cc + nt * 8;
            if (ra < N) {
                *(float2*)(g_H2 + (size_t)ra * NCLS + col) =
                    make_float2(acc[mt][nt][0], acc[mt][nt][1]);
                *(__half2*)(g_H2h + (size_t)ra * NCLS + col) =
                    __floats2half2_rn(acc[mt][nt][0], acc[mt][nt][1]);
            }
            if (rb < N) {
                *(float2*)(g_H2 + (size_t)rb * NCLS + col) =
                    make_float2(acc[mt][nt][2], acc[mt][nt][3]);
                *(__half2*)(g_H2h + (size_t)rb * NCLS + col) =
                    __floats2half2_rn(acc[mt][nt][2], acc[mt][nt][3]);
            }
        }
    }
    #undef LOAD_X2
    #undef CP_B2
    #undef STORE_A2
}

// ==================== layer-2 aggregation (16 lanes per node, fp16 gather) ====================
__global__ __launch_bounds__(256) void k_agg2(const float* __restrict__ b2,
                                              float* __restrict__ out, int N) {
    int t = blockIdx.x * blockDim.x + threadIdx.x;
    int i = t >> 4;
    int c = t & 15;
    if (i >= N) return;

    float di = g_dinv[i];
    float s2 = di * di;
    float4 acc = ((const float4*)b2)[c];
    float4 h   = *((const float4*)(g_H2 + (size_t)i * NCLS) + c);
    acc.x += s2 * h.x; acc.y += s2 * h.y; acc.z += s2 * h.z; acc.w += s2 * h.w;

    int e   = g_rs[i];
    int end = g_rs[i + 1];
    for (; e + 1 < end; e += 2) {
        int2 p0 = g_csr[e];
        int2 p1 = g_csr[e + 1];
        float n0 = __int_as_float(p0.y);
        float n1 = __int_as_float(p1.y);
        uint2 r0 = __ldg((const uint2*)(g_H2h + (size_t)p0.x * NCLS) + c);
        uint2 r1 = __ldg((const uint2*)(g_H2h + (size_t)p1.x * NCLS) + c);
        float2 a0 = __half22float2(*(__half2*)&r0.x);
        float2 a1 = __half22float2(*(__half2*)&r0.y);
        float2 c0 = __half22float2(*(__half2*)&r1.x);
        float2 c1 = __half22float2(*(__half2*)&r1.y);
        acc.x += n0 * a0.x; acc.y += n0 * a0.y; acc.z += n0 * a1.x; acc.w += n0 * a1.y;
        acc.x += n1 * c0.x; acc.y += n1 * c0.y; acc.z += n1 * c1.x; acc.w += n1 * c1.y;
    }
    if (e < end) {
        int2 p0 = g_csr[e];
        float n0 = __int_as_float(p0.y);
        uint2 r0 = __ldg((const uint2*)(g_H2h + (size_t)p0.x * NCLS) + c);
        float2 a0 = __half22float2(*(__half2*)&r0.x);
        float2 a1 = __half22float2(*(__half2*)&r0.y);
        acc.x += n0 * a0.x; acc.y += n0 * a0.y; acc.z += n0 * a1.x; acc.w += n0 * a1.y;
    }

    *((float4*)(out + (size_t)i * NCLS) + c) = acc;
}

// ==================== launch ====================
struct AuxObjs {
    cudaStream_t s1;
    cudaEvent_t  e0, e1;
    AuxObjs() {
        cudaStreamCreateWithFlags(&s1, cudaStreamNonBlocking);
        cudaEventCreateWithFlags(&e0, cudaEventDisableTiming);
        cudaEventCreateWithFlags(&e1, cudaEventDisableTiming);
    }
};

extern "C" void kernel_launch(void* const* d_in, const int* in_sizes, int n_in,
                              void* d_out, int out_size) {
    static AuxObjs aux;

    const float* x  = (const float*)d_in[0];
    const int*   ei = (const int*)  d_in[1];
    const float* W1 = (const float*)d_in[2];
    const float* b1 = (const float*)d_in[3];
    const float* W2 = (const float*)d_in[4];
    const float* b2 = (const float*)d_in[5];
    float* out = (float*)d_out;

    int N = in_sizes[0] / NFEAT;   // 50000
    int E = in_sizes[1] / 2;       // 640000
    int nb = (N + 255) / 256;

    cudaFuncSetAttribute(k_gemm1_mma, cudaFuncAttributeMaxDynamicSharedMemorySize,
                         GSMEM_BYTES);
    cudaFuncSetAttribute(k_gemm2_mma, cudaFuncAttributeMaxDynamicSharedMemorySize,
                         G2SMEM_BYTES);

    // Fork CSR branch onto s1.
    cudaEventRecord(aux.e0, 0);
    cudaStreamWaitEvent(aux.s1, aux.e0, 0);

    k_cnt_init<<<(N + 255) / 256, 256, 0, aux.s1>>>(N);                  // 1
    k_cnt_acc <<<(E + 255) / 256, 256, 0, aux.s1>>>(ei, E);              // 2
    k_prep    <<<(NFEAT * HID + HID * NCLS + 255) / 256, 256>>>(W1, W2); // 3 (main)
    k_gemm1_mma<<<(N + 127) / 128, 256, GSMEM_BYTES>>>(x, N);            // 4 (profiled)
    k_scan1   <<<nb, 256, 0, aux.s1>>>(N);                               // 5
    k_scan2   <<<1, 256, 0, aux.s1>>>(nb, N, E);                         // 6
    k_scan3   <<<nb, 256, 0, aux.s1>>>(N);                               // 7
    k_scatter <<<(E + 255) / 256, 256, 0, aux.s1>>>(ei, E);              // 8
    cudaEventRecord(aux.e1, aux.s1);
    cudaStreamWaitEvent(0, aux.e1, 0);

    k_agg1     <<<(N * 32 + 255) / 256, 256>>>(b1, N);                   // 9
    k_gemm2_mma<<<(N + 127) / 128, 256, G2SMEM_BYTES>>>(N);              // 10
    k_agg2     <<<(N * 16 + 255) / 256, 256>>>(b2, out, N);              // 11
}

// round 9
// speedup vs baseline: 1.5452x; 1.1860x over previous
#include <cuda_runtime.h>
#include <cuda_fp16.h>
#include <cstdint>

#define NFEAT 512
#define HID   128
#define NCLS  64
#define NMAX  50048
#define EMAX  640000

// ---------------- device scratch ----------------
__device__ float g_dinv[NMAX];
__device__ int   g_cnt [NMAX];
__device__ int   g_excl[NMAX];
__device__ int   g_bsum[256];
__device__ int   g_boff[256];
__device__ int   g_rs  [NMAX + 1];
__device__ int   g_cur [NMAX];
__device__ int2  g_csr [EMAX];
__device__ __half g_H1h[(size_t)NMAX * HID];     // layer-1 pre-agg (fp16)
__device__ float  g_agg1[(size_t)NMAX * HID];    // layer-1 post-agg (fp32)
__device__ __half g_H2h[(size_t)NMAX * NCLS];    // layer-2 pre-agg (fp16)
// W1 fp16 hi/lo split, transposed [n][k]
__device__ __half g_Bh[HID * NFEAT];
__device__ __half g_Bl[HID * NFEAT];
// W2 fp16 hi/lo split, transposed [n][k]
__device__ __half g_B2h[NCLS * HID];
__device__ __half g_B2l[NCLS * HID];

// ==================== helpers ====================
__device__ __forceinline__ uint32_t smem_u32(const void* p) {
    uint32_t a;
    asm("{ .reg .u64 t; cvta.to.shared.u64 t, %1; cvt.u32.u64 %0, t; }"
        : "=r"(a) : "l"(p));
    return a;
}
__device__ __forceinline__ void ldm_x4(uint32_t& r0, uint32_t& r1,
                                       uint32_t& r2, uint32_t& r3, uint32_t addr) {
    asm volatile("ldmatrix.sync.aligned.m8n8.x4.shared.b16 {%0,%1,%2,%3}, [%4];"
                 : "=r"(r0), "=r"(r1), "=r"(r2), "=r"(r3) : "r"(addr));
}
__device__ __forceinline__ void mma_f16(float& d0, float& d1, float& d2, float& d3,
                                        uint32_t a0, uint32_t a1, uint32_t a2, uint32_t a3,
                                        uint32_t b0, uint32_t b1) {
    asm volatile(
        "mma.sync.aligned.m16n8k16.row.col.f32.f16.f16.f32 "
        "{%0,%1,%2,%3}, {%4,%5,%6,%7}, {%8,%9}, {%0,%1,%2,%3};"
        : "+f"(d0), "+f"(d1), "+f"(d2), "+f"(d3)
        : "r"(a0), "r"(a1), "r"(a2), "r"(a3), "r"(b0), "r"(b1));
}
__device__ __forceinline__ void cp16(uint32_t dst, const void* src) {
    asm volatile("cp.async.cg.shared.global [%0], [%1], 16;" :: "r"(dst), "l"(src));
}
#define CP_COMMIT() asm volatile("cp.async.commit_group;" ::: "memory")
#define CP_WAIT0()  asm volatile("cp.async.wait_group 0;" ::: "memory")

// ==================== CSR build ====================
__global__ void k_cnt_init(int N) {
    int i = blockIdx.x * blockDim.x + threadIdx.x;
    if (i < N) g_cnt[i] = 0;
}
__global__ void k_cnt_acc(const int* __restrict__ ei, int E) {
    int e = blockIdx.x * blockDim.x + threadIdx.x;
    if (e < E) atomicAdd(&g_cnt[ei[E + e]], 1);
}
__global__ void k_scan1(int N) {
    __shared__ int sh[256];
    int i = blockIdx.x * 256 + threadIdx.x;
    int v = (i < N) ? g_cnt[i] : 0;
    if (i < N) g_dinv[i] = rsqrtf((float)(v + 1));
    sh[threadIdx.x] = v;
    __syncthreads();
    #pragma unroll
    for (int off = 1; off < 256; off <<= 1) {
        int t = (threadIdx.x >= off) ? sh[threadIdx.x - off] : 0;
        __syncthreads();
        sh[threadIdx.x] += t;
        __syncthreads();
    }
    if (i < N) g_excl[i] = sh[threadIdx.x] - v;
    if (threadIdx.x == 255) g_bsum[blockIdx.x] = sh[255];
}
__global__ void k_scan2(int nb, int N, int E) {
    __shared__ int sh[256];
    int v = (threadIdx.x < nb) ? g_bsum[threadIdx.x] : 0;
    sh[threadIdx.x] = v;
    __syncthreads();
    #pragma unroll
    for (int off = 1; off < 256; off <<= 1) {
        int t = (threadIdx.x >= off) ? sh[threadIdx.x - off] : 0;
        __syncthreads();
        sh[threadIdx.x] += t;
        __syncthreads();
    }
    if (threadIdx.x < nb) g_boff[threadIdx.x] = sh[threadIdx.x] - v;
    if (threadIdx.x == 0) g_rs[N] = E;
}
__global__ void k_scan3(int N) {
    int i = blockIdx.x * blockDim.x + threadIdx.x;
    if (i < N) {
        int r = g_excl[i] + g_boff[i >> 8];
        g_rs[i]  = r;
        g_cur[i] = r;
    }
}
__global__ void k_scatter(const int* __restrict__ ei, int E) {
    int e = blockIdx.x * blockDim.x + threadIdx.x;
    if (e >= E) return;
    int s = ei[e];
    int d = ei[E + e];
    int pos = atomicAdd(&g_cur[d], 1);
    g_csr[pos] = make_int2(s, __float_as_int(g_dinv[s] * g_dinv[d]));
}

// ==================== weight prep (fp16 hi/lo, merged W1+W2) ====================
__global__ void k_prep(const float* __restrict__ W1, const float* __restrict__ W2) {
    int t = blockIdx.x * blockDim.x + threadIdx.x;
    if (t < NFEAT * HID) {
        int k = t >> 7;
        int n = t & 127;
        float v = W1[t];
        __half h = __float2half_rn(v);
        __half l = __float2half_rn(v - __half2float(h));
        g_Bh[n * NFEAT + k] = h;
        g_Bl[n * NFEAT + k] = l;
    } else if (t < NFEAT * HID + HID * NCLS) {
        int u = t - NFEAT * HID;
        int k = u >> 6;
        int n = u & 63;
        float v = W2[u];
        __half h = __float2half_rn(v);
        __half l = __float2half_rn(v - __half2float(h));
        g_B2h[n * HID + k] = h;
        g_B2l[n * HID + k] = l;
    }
}

// ==================== GEMM1: H1h = fp16(X) @ (W1h + W1l), 2 MMAs ====================
// smem buffer: A 128x40 fp16 (10240B), Bh (10240B), Bl (10240B) -> 30720B/buf
#define STRB   80
#define BUFSZ  30720
#define OFF_BH 10240
#define OFF_BL 20480
#define NCHUNK (NFEAT / 32)     // 16
#define GSMEM_BYTES (2 * BUFSZ)

extern __shared__ __align__(128) unsigned char s_dyn[];

__global__ void __launch_bounds__(256, 2) k_gemm1_mma(const float* __restrict__ X, int N) {
    uint32_t sb = smem_u32(s_dyn);
    int tid  = threadIdx.x;
    int wid  = tid >> 5;
    int lane = tid & 31;
    int warp_m = (wid & 3) * 32;
    int warp_n = (wid >> 2) * 64;
    int rowBase = blockIdx.x * 128;

    float acc[2][8][4];
    #pragma unroll
    for (int mt = 0; mt < 2; mt++)
        #pragma unroll
        for (int nt = 0; nt < 8; nt++)
            #pragma unroll
            for (int j = 0; j < 4; j++) acc[mt][nt][j] = 0.0f;

    float4 xs[4];
    int xrow = tid >> 3;
    int xseg = tid & 7;
    int bn   = tid >> 2;
    int bseg = tid & 3;

    #define LOAD_X(c)                                                          \
        {                                                                      \
            _Pragma("unroll")                                                  \
            for (int i = 0; i < 4; i++) {                                      \
                int row = xrow + 32 * i;                                       \
                int grow = rowBase + row;                                      \
                if (grow > N - 1) grow = N - 1;                                \
                xs[i] = *(const float4*)(X + (size_t)grow * NFEAT + (c) * 32 + xseg * 4); \
            }                                                                  \
        }
    #define CP_B(c, b)                                                         \
        {                                                                      \
            _Pragma("unroll")                                                  \
            for (int i = 0; i < 2; i++) {                                      \
                int n = bn + 64 * i;                                           \
                uint32_t dst = sb + (b) * BUFSZ + OFF_BH + n * STRB + bseg * 16; \
                cp16(dst, g_Bh + (size_t)n * NFEAT + (c) * 32 + bseg * 8);      \
                cp16(dst + (OFF_BL - OFF_BH),                                   \
                     g_Bl + (size_t)n * NFEAT + (c) * 32 + bseg * 8);           \
            }                                                                  \
        }
    #define STORE_A(b)                                                         \
        {                                                                      \
            unsigned char* base = s_dyn + (b) * BUFSZ;                         \
            _Pragma("unroll")                                                  \
            for (int i = 0; i < 4; i++) {                                      \
                int row = xrow + 32 * i;                                       \
                __half2 p0 = __floats2half2_rn(xs[i].x, xs[i].y);              \
                __half2 p1 = __floats2half2_rn(xs[i].z, xs[i].w);              \
                uint32_t off = row * STRB + xseg * 8;                          \
                *(uint2*)(base + off) =                                        \
                    make_uint2(*(uint32_t*)&p0, *(uint32_t*)&p1);              \
            }                                                                  \
        }

    CP_B(0, 0); CP_COMMIT();
    LOAD_X(0);
    STORE_A(0);
    CP_WAIT0();
    __syncthreads();

    uint32_t aRowOff = (warp_m + (lane & 15)) * STRB + ((lane & 16) ? 16 : 0);
    uint32_t bRowSel = (lane & 7) + ((lane & 16) ? 8 : 0);
    uint32_t bKoff   = (lane & 8) ? 16 : 0;

    #pragma unroll 1
    for (int c = 0; c < NCHUNK; c++) {
        int cur = c & 1;
        if (c + 1 < NCHUNK) {
            CP_B(c + 1, cur ^ 1); CP_COMMIT();
            LOAD_X(c + 1);
        }

        uint32_t base = sb + cur * BUFSZ;
        #pragma unroll
        for (int ka = 0; ka < 2; ka++) {
            uint32_t k0b = ka * 32;

            uint32_t a[2][4];
            #pragma unroll
            for (int mt = 0; mt < 2; mt++) {
                uint32_t aaddr = base + aRowOff + mt * (16 * STRB) + k0b;
                ldm_x4(a[mt][0], a[mt][1], a[mt][2], a[mt][3], aaddr);
            }

            uint32_t bh[8][2], bl[8][2];
            #pragma unroll
            for (int np = 0; np < 4; np++) {
                uint32_t brow = warp_n + np * 16 + bRowSel;
                uint32_t baddr = base + OFF_BH + brow * STRB + k0b + bKoff;
                ldm_x4(bh[2*np][0], bh[2*np][1], bh[2*np+1][0], bh[2*np+1][1], baddr);
                ldm_x4(bl[2*np][0], bl[2*np][1], bl[2*np+1][0], bl[2*np+1][1],
                       baddr + (OFF_BL - OFF_BH));
            }

            #pragma unroll
            for (int mt = 0; mt < 2; mt++)
                #pragma unroll
                for (int nt = 0; nt < 8; nt++) {
                    mma_f16(acc[mt][nt][0], acc[mt][nt][1], acc[mt][nt][2], acc[mt][nt][3],
                            a[mt][0], a[mt][1], a[mt][2], a[mt][3],
                            bh[nt][0], bh[nt][1]);
                    mma_f16(acc[mt][nt][0], acc[mt][nt][1], acc[mt][nt][2], acc[mt][nt][3],
                            a[mt][0], a[mt][1], a[mt][2], a[mt][3],
                            bl[nt][0], bl[nt][1]);
                }
        }

        if (c + 1 < NCHUNK) {
            STORE_A(cur ^ 1);
            CP_WAIT0();
        }
        __syncthreads();
    }

    int r0 = rowBase + warp_m + (lane >> 2);
    int cc = warp_n + 2 * (lane & 3);
    #pragma unroll
    for (int mt = 0; mt < 2; mt++) {
        int ra = r0 + mt * 16;
        int rb = ra + 8;
        #pragma unroll
        for (int nt = 0; nt < 8; nt++) {
            int col = cc + nt * 8;
            if (ra < N)
                *(__half2*)(g_H1h + (size_t)ra * HID + col) =
                    __floats2half2_rn(acc[mt][nt][0], acc[mt][nt][1]);
            if (rb < N)
                *(__half2*)(g_H1h + (size_t)rb * HID + col) =
                    __floats2half2_rn(acc[mt][nt][2], acc[mt][nt][3]);
        }
    }
    #undef LOAD_X
    #undef CP_B
    #undef STORE_A
}

// ==================== layer-1 aggregation (warp per node, fp16 gather) ====================
__global__ __launch_bounds__(256) void k_agg1(const float* __restrict__ b1, int N) {
    int w    = (blockIdx.x * blockDim.x + threadIdx.x) >> 5;
    int lane = threadIdx.x & 31;
    if (w >= N) return;

    float di = g_dinv[w];
    float s2 = di * di;
    float4 acc = ((const float4*)b1)[lane];
    {
        uint2 rs = *((const uint2*)(g_H1h + (size_t)w * HID) + lane);
        float2 h0 = __half22float2(*(__half2*)&rs.x);
        float2 h1 = __half22float2(*(__half2*)&rs.y);
        acc.x += s2 * h0.x; acc.y += s2 * h0.y; acc.z += s2 * h1.x; acc.w += s2 * h1.y;
    }

    int e   = g_rs[w];
    int end = g_rs[w + 1];
    for (; e + 1 < end; e += 2) {
        int2 p0 = g_csr[e];
        int2 p1 = g_csr[e + 1];
        float n0 = __int_as_float(p0.y);
        float n1 = __int_as_float(p1.y);
        uint2 r0 = __ldg((const uint2*)(g_H1h + (size_t)p0.x * HID) + lane);
        uint2 r1 = __ldg((const uint2*)(g_H1h + (size_t)p1.x * HID) + lane);
        float2 a0 = __half22float2(*(__half2*)&r0.x);
        float2 a1 = __half22float2(*(__half2*)&r0.y);
        float2 c0 = __half22float2(*(__half2*)&r1.x);
        float2 c1 = __half22float2(*(__half2*)&r1.y);
        acc.x += n0 * a0.x; acc.y += n0 * a0.y; acc.z += n0 * a1.x; acc.w += n0 * a1.y;
        acc.x += n1 * c0.x; acc.y += n1 * c0.y; acc.z += n1 * c1.x; acc.w += n1 * c1.y;
    }
    if (e < end) {
        int2 p0 = g_csr[e];
        float n0 = __int_as_float(p0.y);
        uint2 r0 = __ldg((const uint2*)(g_H1h + (size_t)p0.x * HID) + lane);
        float2 a0 = __half22float2(*(__half2*)&r0.x);
        float2 a1 = __half22float2(*(__half2*)&r0.y);
        acc.x += n0 * a0.x; acc.y += n0 * a0.y; acc.z += n0 * a1.x; acc.w += n0 * a1.y;
    }

    acc.x = fmaxf(acc.x, 0.f); acc.y = fmaxf(acc.y, 0.f);
    acc.z = fmaxf(acc.z, 0.f); acc.w = fmaxf(acc.w, 0.f);
    *((float4*)(g_agg1 + (size_t)w * HID) + lane) = acc;
}

// ==================== GEMM2: H2h = fp16(agg1) @ (W2h + W2l), 2 MMAs ====================
// smem buffer: A 128x40 fp16 (10240B), B2h 64x40 (5120B), B2l (5120B) -> 20480B/buf
#define BUF2SZ  20480
#define OFF2_BH 10240
#define OFF2_BL 15360
#define NCHUNK2 (HID / 32)      // 4
#define G2SMEM_BYTES (2 * BUF2SZ)

__global__ void __launch_bounds__(256) k_gemm2_mma(int N) {
    uint32_t sb = smem_u32(s_dyn);
    int tid  = threadIdx.x;
    int wid  = tid >> 5;
    int lane = tid & 31;
    int warp_m = (wid & 3) * 32;
    int warp_n = (wid >> 2) * 32;
    int rowBase = blockIdx.x * 128;

    float acc[2][4][4];
    #pragma unroll
    for (int mt = 0; mt < 2; mt++)
        #pragma unroll
        for (int nt = 0; nt < 4; nt++)
            #pragma unroll
            for (int j = 0; j < 4; j++) acc[mt][nt][j] = 0.0f;

    float4 xs[4];
    int xrow = tid >> 3;
    int xseg = tid & 7;
    int bn   = tid >> 2;   // 0..63
    int bseg = tid & 3;

    #define LOAD_X2(c)                                                         \
        {                                                                      \
            _Pragma("unroll")                                                  \
            for (int i = 0; i < 4; i++) {                                      \
                int row = xrow + 32 * i;                                       \
                int grow = rowBase + row;                                      \
                if (grow > N - 1) grow = N - 1;                                \
                xs[i] = *(const float4*)(g_agg1 + (size_t)grow * HID + (c) * 32 + xseg * 4); \
            }                                                                  \
        }
    #define CP_B2(c, b)                                                        \
        {                                                                      \
            uint32_t dst = sb + (b) * BUF2SZ + OFF2_BH + bn * STRB + bseg * 16; \
            cp16(dst, g_B2h + (size_t)bn * HID + (c) * 32 + bseg * 8);          \
            cp16(dst + (OFF2_BL - OFF2_BH),                                     \
                 g_B2l + (size_t)bn * HID + (c) * 32 + bseg * 8);               \
        }
    #define STORE_A2(b)                                                        \
        {                                                                      \
            unsigned char* base = s_dyn + (b) * BUF2SZ;                        \
            _Pragma("unroll")                                                  \
            for (int i = 0; i < 4; i++) {                                      \
                int row = xrow + 32 * i;                                       \
                __half2 p0 = __floats2half2_rn(xs[i].x, xs[i].y);              \
                __half2 p1 = __floats2half2_rn(xs[i].z, xs[i].w);              \
                uint32_t off = row * STRB + xseg * 8;                          \
                *(uint2*)(base + off) =                                        \
                    make_uint2(*(uint32_t*)&p0, *(uint32_t*)&p1);              \
            }                                                                  \
        }

    CP_B2(0, 0); CP_COMMIT();
    LOAD_X2(0);
    STORE_A2(0);
    CP_WAIT0();
    __syncthreads();

    uint32_t aRowOff = (warp_m + (lane & 15)) * STRB + ((lane & 16) ? 16 : 0);
    uint32_t bRowSel = (lane & 7) + ((lane & 16) ? 8 : 0);
    uint32_t bKoff   = (lane & 8) ? 16 : 0;

    #pragma unroll 1
    for (int c = 0; c < NCHUNK2; c++) {
        int cur = c & 1;
        if (c + 1 < NCHUNK2) {
            CP_B2(c + 1, cur ^ 1); CP_COMMIT();
            LOAD_X2(c + 1);
        }

        uint32_t base = sb + cur * BUF2SZ;
        #pragma unroll
        for (int ka = 0; ka < 2; ka++) {
            uint32_t k0b = ka * 32;

            uint32_t a[2][4];
            #pragma unroll
            for (int mt = 0; mt < 2; mt++) {
                uint32_t aaddr = base + aRowOff + mt * (16 * STRB) + k0b;
                ldm_x4(a[mt][0], a[mt][1], a[mt][2], a[mt][3], aaddr);
            }

            uint32_t bh[4][2], bl[4][2];
            #pragma unroll
            for (int np = 0; np < 2; np++) {
                uint32_t brow = warp_n + np * 16 + bRowSel;
                uint32_t baddr = base + OFF2_BH + brow * STRB + k0b + bKoff;
                ldm_x4(bh[2*np][0], bh[2*np][1], bh[2*np+1][0], bh[2*np+1][1], baddr);
                ldm_x4(bl[2*np][0], bl[2*np][1], bl[2*np+1][0], bl[2*np+1][1],
                       baddr + (OFF2_BL - OFF2_BH));
            }

            #pragma unroll
            for (int mt = 0; mt < 2; mt++)
                #pragma unroll
                for (int nt = 0; nt < 4; nt++) {
                    mma_f16(acc[mt][nt][0], acc[mt][nt][1], acc[mt][nt][2], acc[mt][nt][3],
                            a[mt][0], a[mt][1], a[mt][2], a[mt][3],
                            bh[nt][0], bh[nt][1]);
                    mma_f16(acc[mt][nt][0], acc[mt][nt][1], acc[mt][nt][2], acc[mt][nt][3],
                            a[mt][0], a[mt][1], a[mt][2], a[mt][3],
                            bl[nt][0], bl[nt][1]);
                }
        }

        if (c + 1 < NCHUNK2) {
            STORE_A2(cur ^ 1);
            CP_WAIT0();
        }
        __syncthreads();
    }

    int r0 = rowBase + warp_m + (lane >> 2);
    int cc = warp_n + 2 * (lane & 3);
    #pragma unroll
    for (int mt = 0; mt < 2; mt++) {
        int ra = r0 + mt * 16;
        int rb = ra + 8;
        #pragma unroll
        for (int nt = 0; nt < 4; nt++) {
            int col = cc + nt * 8;
            if (ra < N)
                *(__half2*)(g_H2h + (size_t)ra * NCLS + col) =
                    __floats2half2_rn(acc[mt][nt][0], acc[mt][nt][1]);
            if (rb < N)
                *(__half2*)(g_H2h + (size_t)rb * NCLS + col) =
                    __floats2half2_rn(acc[mt][nt][2], acc[mt][nt][3]);
        }
    }
    #undef LOAD_X2
    #undef CP_B2
    #undef STORE_A2
}

// ==================== layer-2 aggregation (16 lanes per node, fp16 gather) ====================
__global__ __launch_bounds__(256) void k_agg2(const float* __restrict__ b2,
                                              float* __restrict__ out, int N) {
    int t = blockIdx.x * blockDim.x + threadIdx.x;
    int i = t >> 4;
    int c = t & 15;
    if (i >= N) return;

    float di = g_dinv[i];
    float s2 = di * di;
    float4 acc = ((const float4*)b2)[c];
    {
        uint2 rs = *((const uint2*)(g_H2h + (size_t)i * NCLS) + c);
        float2 h0 = __half22float2(*(__half2*)&rs.x);
        float2 h1 = __half22float2(*(__half2*)&rs.y);
        acc.x += s2 * h0.x; acc.y += s2 * h0.y; acc.z += s2 * h1.x; acc.w += s2 * h1.y;
    }

    int e   = g_rs[i];
    int end = g_rs[i + 1];
    for (; e + 1 < end; e += 2) {
        int2 p0 = g_csr[e];
        int2 p1 = g_csr[e + 1];
        float n0 = __int_as_float(p0.y);
        float n1 = __int_as_float(p1.y);
        uint2 r0 = __ldg((const uint2*)(g_H2h + (size_t)p0.x * NCLS) + c);
        uint2 r1 = __ldg((const uint2*)(g_H2h + (size_t)p1.x * NCLS) + c);
        float2 a0 = __half22float2(*(__half2*)&r0.x);
        float2 a1 = __half22float2(*(__half2*)&r0.y);
        float2 c0 = __half22float2(*(__half2*)&r1.x);
        float2 c1 = __half22float2(*(__half2*)&r1.y);
        acc.x += n0 * a0.x; acc.y += n0 * a0.y; acc.z += n0 * a1.x; acc.w += n0 * a1.y;
        acc.x += n1 * c0.x; acc.y += n1 * c0.y; acc.z += n1 * c1.x; acc.w += n1 * c1.y;
    }
    if (e < end) {
        int2 p0 = g_csr[e];
        float n0 = __int_as_float(p0.y);
        uint2 r0 = __ldg((const uint2*)(g_H2h + (size_t)p0.x * NCLS) + c);
        float2 a0 = __half22float2(*(__half2*)&r0.x);
        float2 a1 = __half22float2(*(__half2*)&r0.y);
        acc.x += n0 * a0.x; acc.y += n0 * a0.y; acc.z += n0 * a1.x; acc.w += n0 * a1.y;
    }

    *((float4*)(out + (size_t)i * NCLS) + c) = acc;
}

// ==================== launch ====================
struct AuxObjs {
    cudaStream_t s1;
    cudaEvent_t  e0, e1;
    AuxObjs() {
        cudaStreamCreateWithFlags(&s1, cudaStreamNonBlocking);
        cudaEventCreateWithFlags(&e0, cudaEventDisableTiming);
        cudaEventCreateWithFlags(&e1, cudaEventDisableTiming);
    }
};

extern "C" void kernel_launch(void* const* d_in, const int* in_sizes, int n_in,
                              void* d_out, int out_size) {
    static AuxObjs aux;

    const float* x  = (const float*)d_in[0];
    const int*   ei = (const int*)  d_in[1];
    const float* W1 = (const float*)d_in[2];
    const float* b1 = (const float*)d_in[3];
    const float* W2 = (const float*)d_in[4];
    const float* b2 = (const float*)d_in[5];
    float* out = (float*)d_out;

    int N = in_sizes[0] / NFEAT;   // 50000
    int E = in_sizes[1] / 2;       // 640000
    int nb = (N + 255) / 256;

    cudaFuncSetAttribute(k_gemm1_mma, cudaFuncAttributeMaxDynamicSharedMemorySize,
                         GSMEM_BYTES);
    cudaFuncSetAttribute(k_gemm2_mma, cudaFuncAttributeMaxDynamicSharedMemorySize,
                         G2SMEM_BYTES);

    // Fork CSR branch onto s1.
    cudaEventRecord(aux.e0, 0);
    cudaStreamWaitEvent(aux.s1, aux.e0, 0);

    k_cnt_init<<<(N + 255) / 256, 256, 0, aux.s1>>>(N);                  // 1
    k_cnt_acc <<<(E + 255) / 256, 256, 0, aux.s1>>>(ei, E);              // 2
    k_prep    <<<(NFEAT * HID + HID * NCLS + 255) / 256, 256>>>(W1, W2); // 3 (main)
    k_gemm1_mma<<<(N + 127) / 128, 256, GSMEM_BYTES>>>(x, N);            // 4 (profiled)
    k_scan1   <<<nb, 256, 0, aux.s1>>>(N);                               // 5
    k_scan2   <<<1, 256, 0, aux.s1>>>(nb, N, E);                         // 6
    k_scan3   <<<nb, 256, 0, aux.s1>>>(N);                               // 7
    k_scatter <<<(E + 255) / 256, 256, 0, aux.s1>>>(ei, E);              // 8
    cudaEventRecord(aux.e1, aux.s1);
    cudaStreamWaitEvent(0, aux.e1, 0);

    k_agg1     <<<(N * 32 + 255) / 256, 256>>>(b1, N);                   // 9
    k_gemm2_mma<<<(N + 127) / 128, 256, G2SMEM_BYTES>>>(N);              // 10
    k_agg2     <<<(N * 16 + 255) / 256, 256>>>(b2, out, N);              // 11
}